// round 15
// baseline (speedup 1.0000x reference)
#include <cuda_runtime.h>
#include <cuda_bf16.h>
#include <math.h>
#include <stdint.h>

// ---------------- sizes ----------------
#define MTOK 8192
#define DMODEL 256
#define HID 1024

// ---------------- fp32 scratch ----------------
__device__ float g_X[MTOK*DMODEL];
__device__ float g_T[MTOK*DMODEL];
__device__ float g_H[MTOK*DMODEL];
__device__ float g_QKV[MTOK*3*DMODEL];
__device__ float g_POS[512*DMODEL];
__device__ float g_BNP[2*64*DMODEL];
__device__ float g_PF[16*327680];
__device__ float g_FP[640*16*128];
__device__ float g_ADD[16*128];

// ---------------- bf16 hi/lo packed-pair scratch ([m][k/2] uint32) --------
__device__ uint32_t g_Xh[MTOK*128], g_Xl[MTOK*128];
__device__ uint32_t g_Hh[MTOK*128], g_Hl[MTOK*128];
__device__ uint32_t g_Th[MTOK*128], g_Tl[MTOK*128];
__device__ uint32_t g_Gh[MTOK*512], g_Gl[MTOK*512];
__device__ uint32_t g_Fh[MTOK*128], g_Fl[MTOK*128];
__device__ uint32_t g_AOh[MTOK*128], g_AOl[MTOK*128];
__device__ uint32_t g_Wph[256*128],  g_Wpl[256*128];
__device__ uint32_t g_W1h[1024*128], g_W1l[1024*128];
__device__ uint32_t g_W2h[256*512],  g_W2l[256*512];
__device__ uint32_t g_Wqh[768*128],  g_Wql[768*128];
__device__ uint32_t g_Woh[256*128],  g_Wol[256*128];
__device__ uint32_t g_Pyh[5*128*128], g_Pyl[5*128*128];

// ---------------- helpers ----------------
__device__ __forceinline__ float gelu_tanh(float x) {
    float x3 = x*x*x;
    float u = 0.7978845608028654f*(x + 0.044715f*x3);
    float th = 1.f - 2.f/(__expf(2.f*u) + 1.f);
    return 0.5f*x*(1.f + th);
}

__device__ __forceinline__ void split_pack(float v0, float v1, uint32_t& ph, uint32_t& pl) {
    __nv_bfloat16 h0 = __float2bfloat16(v0), h1 = __float2bfloat16(v1);
    float r0 = v0 - __bfloat162float(h0), r1 = v1 - __bfloat162float(h1);
    __nv_bfloat16 l0 = __float2bfloat16(r0), l1 = __float2bfloat16(r1);
    ph = ((uint32_t)__bfloat16_as_ushort(h1) << 16) | (uint32_t)__bfloat16_as_ushort(h0);
    pl = ((uint32_t)__bfloat16_as_ushort(l1) << 16) | (uint32_t)__bfloat16_as_ushort(l0);
}

__device__ __forceinline__ void mma_bf16(float c[4],
    uint32_t a0, uint32_t a1, uint32_t a2, uint32_t a3, uint32_t b0, uint32_t b1)
{
    asm volatile(
        "mma.sync.aligned.m16n8k16.row.col.f32.bf16.bf16.f32 "
        "{%0,%1,%2,%3}, {%4,%5,%6,%7}, {%8,%9}, {%0,%1,%2,%3};\n"
        : "+f"(c[0]), "+f"(c[1]), "+f"(c[2]), "+f"(c[3])
        : "r"(a0), "r"(a1), "r"(a2), "r"(a3), "r"(b0), "r"(b1));
}

__device__ __forceinline__ uint32_t smem_u32(const void* p) {
    uint32_t a;
    asm("{ .reg .u64 t; cvta.to.shared.u64 t, %1; cvt.u32.u64 %0, t; }" : "=r"(a) : "l"(p));
    return a;
}

__device__ __forceinline__ void cp16(uint32_t dst, const void* src) {
    asm volatile("cp.async.cg.shared.global [%0], [%1], 16;" :: "r"(dst), "l"(src));
}

__device__ __forceinline__ void ldsm_x4(uint32_t r[4], uint32_t addr) {
    asm volatile("ldmatrix.sync.aligned.m8n8.x4.shared.b16 {%0,%1,%2,%3}, [%4];"
        : "=r"(r[0]), "=r"(r[1]), "=r"(r[2]), "=r"(r[3]) : "r"(addr));
}

// ---------------- one-shot weight conversion ----------------
__global__ void wcvt_all(
    const float* __restrict__ pW, const float* __restrict__ w1, const float* __restrict__ w2,
    const float* __restrict__ wq, const float* __restrict__ wo, const float* __restrict__ py,
    uint32_t* __restrict__ Wph, uint32_t* __restrict__ Wpl,
    uint32_t* __restrict__ W1h, uint32_t* __restrict__ W1l,
    uint32_t* __restrict__ W2h, uint32_t* __restrict__ W2l,
    uint32_t* __restrict__ Wqh, uint32_t* __restrict__ Wql,
    uint32_t* __restrict__ Woh, uint32_t* __restrict__ Wol,
    uint32_t* __restrict__ Pyh, uint32_t* __restrict__ Pyl)
{
    int idx = blockIdx.x*256 + threadIdx.x;
    const float* src; uint32_t *dh, *dl; int KP, N, li;
    if (idx < 32768)       { src = pW; dh = Wph; dl = Wpl; KP = 128; N = 256; li = idx; }
    else if (idx < 163840) { src = w1; dh = W1h; dl = W1l; KP = 128; N = 1024; li = idx - 32768; }
    else if (idx < 294912) { src = w2; dh = W2h; dl = W2l; KP = 512; N = 256; li = idx - 163840; }
    else if (idx < 393216) { src = wq; dh = Wqh; dl = Wql; KP = 128; N = 768; li = idx - 294912; }
    else if (idx < 425984) { src = wo; dh = Woh; dl = Wol; KP = 128; N = 256; li = idx - 393216; }
    else if (idx < 507904) {
        int r = idx - 425984;
        int l = r >> 14, rem = r & 16383;
        src = py + (size_t)l*32768; dh = Pyh + l*16384; dl = Pyl + l*16384;
        KP = 128; N = 128; li = rem;
    } else return;
    int n = li / KP, kp = li - n*KP;
    float v0 = src[(size_t)(2*kp)*N + n];
    float v1 = src[(size_t)(2*kp+1)*N + n];
    split_pack(v0, v1, dh[li], dl[li]);
}

__global__ void xcvt_k(const float* __restrict__ X, uint32_t* __restrict__ Xh,
                       uint32_t* __restrict__ Xl) {
    int idx = blockIdx.x*256 + threadIdx.x;
    float2 v = *(const float2*)&X[(size_t)idx*2];
    split_pack(v.x, v.y, Xh[idx], Xl[idx]);
}

// ---------------- positional table ----------------
__global__ void pos_k(float* __restrict__ pos) {
    int idx = blockIdx.x*256 + threadIdx.x;
    if (idx >= 512*256) return;
    int n = idx >> 8, d = idx & 255;
    double ang = (double)n / pow(10000.0, (double)(2*(d>>1)) / 256.0);
    pos[idx] = (float)((d & 1) ? cos(ang) : sin(ang));
}

// ---------------- bf16x3 tensor-core GEMM (R6/R11 known-good) ----------------
#define E_NONE 0
#define E_GELU 1
#define E_ADD  2
#define E_PYR  3
#define E_CVT  4

#define GST_W   10240
#define GARR_B  (2560*4)
#define GSM_BYTES (2*GST_W*4)

template<int EPI>
__global__ __launch_bounds__(256, 2) void gemm_bf(
    const uint32_t* __restrict__ Ahg, const uint32_t* __restrict__ Alg,
    const uint32_t* __restrict__ Bhg, const uint32_t* __restrict__ Blg,
    const float* __restrict__ bias, const float* __restrict__ R,
    float* __restrict__ C, uint32_t* __restrict__ Ch, uint32_t* __restrict__ Cl,
    float* __restrict__ BNPp, int M, int Nc, int K, int pyr_base)
{
    extern __shared__ uint32_t smem[];
    uint32_t sbase = smem_u32(smem);

    int t = threadIdx.x;
    int lane = t & 31, warp = t >> 5;
    int g = lane >> 2, tid4 = lane & 3;
    int warpM = (warp & 3) * 32;
    int warpN = (warp >> 2) * 64;
    int bm = blockIdx.y * 128, bn = blockIdx.x * 128;
    int KP = K >> 1;

    int rowA = (lane & 7) + ((lane >> 3) & 1) * 8;
    int kpA  = (lane >> 4) * 4;
    uint32_t aBase = sbase + (uint32_t)(((warpM + rowA)*20 + kpA) * 4);
    int rowB = (lane & 7) + (lane >> 4) * 8;
    int kpB  = ((lane >> 3) & 1) * 4;
    uint32_t bBase = sbase + 2u*GARR_B + (uint32_t)(((warpN + rowB)*20 + kpB) * 4);

    int c0r = t >> 2,        c0k = (t & 3) * 4;
    int c1r = (t + 256) >> 2, c1k = ((t + 256) & 3) * 4;

    float acc[2][8][4];
    #pragma unroll
    for (int i = 0; i < 2; i++)
        #pragma unroll
        for (int j = 0; j < 8; j++)
            #pragma unroll
            for (int r = 0; r < 4; r++) acc[i][j][r] = 0.f;

    int ntile = K >> 5;

    {
        uint32_t d0 = sbase + (uint32_t)((c0r*20 + c0k)*4);
        uint32_t d1 = sbase + (uint32_t)((c1r*20 + c1k)*4);
        cp16(d0,            Ahg + (size_t)(bm + c0r)*KP + c0k);
        cp16(d1,            Ahg + (size_t)(bm + c1r)*KP + c1k);
        cp16(d0 + GARR_B,   Alg + (size_t)(bm + c0r)*KP + c0k);
        cp16(d1 + GARR_B,   Alg + (size_t)(bm + c1r)*KP + c1k);
        cp16(d0 + 2*GARR_B, Bhg + (size_t)(bn + c0r)*KP + c0k);
        cp16(d1 + 2*GARR_B, Bhg + (size_t)(bn + c1r)*KP + c1k);
        cp16(d0 + 3*GARR_B, Blg + (size_t)(bn + c0r)*KP + c0k);
        cp16(d1 + 3*GARR_B, Blg + (size_t)(bn + c1r)*KP + c1k);
        asm volatile("cp.async.commit_group;");
    }

    for (int kt = 0; kt < ntile; kt++) {
        if (kt + 1 < ntile) {
            int kp0 = (kt + 1) * 16;
            uint32_t sb = sbase + (uint32_t)(((kt + 1) & 1) * GST_W * 4);
            uint32_t d0 = sb + (uint32_t)((c0r*20 + c0k)*4);
            uint32_t d1 = sb + (uint32_t)((c1r*20 + c1k)*4);
            cp16(d0,            Ahg + (size_t)(bm + c0r)*KP + kp0 + c0k);
            cp16(d1,            Ahg + (size_t)(bm + c1r)*KP + kp0 + c1k);
            cp16(d0 + GARR_B,   Alg + (size_t)(bm + c0r)*KP + kp0 + c0k);
            cp16(d1 + GARR_B,   Alg + (size_t)(bm + c1r)*KP + kp0 + c1k);
            cp16(d0 + 2*GARR_B, Bhg + (size_t)(bn + c0r)*KP + kp0 + c0k);
            cp16(d1 + 2*GARR_B, Bhg + (size_t)(bn + c1r)*KP + kp0 + c1k);
            cp16(d0 + 3*GARR_B, Blg + (size_t)(bn + c0r)*KP + kp0 + c0k);
            cp16(d1 + 3*GARR_B, Blg + (size_t)(bn + c1r)*KP + kp0 + c1k);
            asm volatile("cp.async.commit_group;");
            asm volatile("cp.async.wait_group 1;");
        } else {
            asm volatile("cp.async.wait_group 0;");
        }
        __syncthreads();

        uint32_t soff = (uint32_t)((kt & 1) * GST_W * 4);
        #pragma unroll
        for (int ko = 0; ko < 16; ko += 8) {
            uint32_t ah[2][4], al[2][4];
            #pragma unroll
            for (int mt = 0; mt < 2; mt++) {
                uint32_t aoff = soff + (uint32_t)((mt*16*20 + ko)*4);
                ldsm_x4(ah[mt], aBase + aoff);
                ldsm_x4(al[mt], aBase + aoff + GARR_B);
            }
            #pragma unroll
            for (int gb = 0; gb < 4; gb++) {
                uint32_t boff = soff + (uint32_t)((gb*16*20 + ko)*4);
                uint32_t bh[4], bl[4];
                ldsm_x4(bh, bBase + boff);
                ldsm_x4(bl, bBase + boff + GARR_B);
                #pragma unroll
                for (int half = 0; half < 2; half++) {
                    int nt = gb*2 + half;
                    uint32_t bh0 = bh[half*2], bh1 = bh[half*2+1];
                    uint32_t bl0 = bl[half*2], bl1 = bl[half*2+1];
                    #pragma unroll
                    for (int mt = 0; mt < 2; mt++) {
                        mma_bf16(acc[mt][nt], ah[mt][0], ah[mt][1], ah[mt][2], ah[mt][3], bh0, bh1);
                        mma_bf16(acc[mt][nt], ah[mt][0], ah[mt][1], ah[mt][2], ah[mt][3], bl0, bl1);
                        mma_bf16(acc[mt][nt], al[mt][0], al[mt][1], al[mt][2], al[mt][3], bh0, bh1);
                    }
                }
            }
        }
        __syncthreads();
    }

    float* sred = (float*)smem;
    int NP = Nc >> 1;
    #pragma unroll
    for (int nt = 0; nt < 8; nt++) {
        int col = bn + warpN + nt*8 + tid4*2;
        float bv0 = bias[col], bv1 = bias[col+1];
        float s0 = 0.f, q0 = 0.f, s1 = 0.f, q1 = 0.f;
        #pragma unroll
        for (int mt = 0; mt < 2; mt++) {
            #pragma unroll
            for (int h = 0; h < 2; h++) {
                int row = bm + warpM + mt*16 + g + h*8;
                float v0 = acc[mt][nt][h*2+0] + bv0;
                float v1 = acc[mt][nt][h*2+1] + bv1;
                if (EPI == E_GELU) { v0 = gelu_tanh(v0); v1 = gelu_tanh(v1); }
                if (EPI == E_ADD) {
                    float2 r = *(const float2*)&R[(size_t)row*Nc + col];
                    v0 += r.x; v1 += r.y;
                    s0 += v0; q0 += v0*v0; s1 += v1; q1 += v1*v1;
                }
                if (EPI == E_GELU || EPI == E_CVT) {
                    uint32_t ph, pl;
                    split_pack(v0, v1, ph, pl);
                    size_t pi = (size_t)row*NP + (col >> 1);
                    Ch[pi] = ph; Cl[pi] = pl;
                } else if (EPI == E_PYR) {
                    long b0 = (long)(row >> 9)*327680 + pyr_base + (row & 511);
                    C[b0 + (long)col*512]     = v0;
                    C[b0 + (long)(col+1)*512] = v1;
                } else {
                    float2 o; o.x = v0; o.y = v1;
                    *(float2*)&C[(size_t)row*Nc + col] = o;
                }
            }
        }
        if (EPI == E_ADD) {
            #pragma unroll
            for (int o = 4; o <= 16; o <<= 1) {
                s0 += __shfl_xor_sync(~0u, s0, o);
                q0 += __shfl_xor_sync(~0u, q0, o);
                s1 += __shfl_xor_sync(~0u, s1, o);
                q1 += __shfl_xor_sync(~0u, q1, o);
            }
            if (g == 0) {
                int cc = warpN + nt*8 + tid4*2;
                int strip = warp & 3;
                sred[strip*128 + cc]       = s0;
                sred[strip*128 + cc + 1]   = s1;
                sred[512 + strip*128 + cc]     = q0;
                sred[512 + strip*128 + cc + 1] = q1;
            }
        }
    }
    if (EPI == E_ADD) {
        __syncthreads();
        if (t < 128) {
            float s = sred[t] + sred[128 + t] + sred[256 + t] + sred[384 + t];
            BNPp[blockIdx.y*256 + blockIdx.x*128 + t] = s;
        } else if (t < 256) {
            int c = t - 128;
            float q = sred[512 + c] + sred[640 + c] + sred[768 + c] + sred[896 + c];
            BNPp[16384 + blockIdx.y*256 + blockIdx.x*128 + c] = q;
        }
    }
}

// ---------------- LayerNorm + pos ----------------
__global__ __launch_bounds__(256) void ln_pos_k(
    const float* __restrict__ T, const float* __restrict__ g,
    const float* __restrict__ b, const float* __restrict__ pos,
    float* __restrict__ H, uint32_t* __restrict__ Hh, uint32_t* __restrict__ Hl)
{
    int warp = threadIdx.x >> 5, lane = threadIdx.x & 31;
    int row = blockIdx.x*8 + warp;
    const float* tr = T + (size_t)row*256;
    float2 v[4]; float s = 0.f, q = 0.f;
    #pragma unroll
    for (int i = 0; i < 4; i++) {
        v[i] = *(const float2*)&tr[2*(i*32 + lane)];
        s += v[i].x + v[i].y; q += v[i].x*v[i].x + v[i].y*v[i].y;
    }
    #pragma unroll
    for (int o = 16; o; o >>= 1) {
        s += __shfl_xor_sync(~0u, s, o);
        q += __shfl_xor_sync(~0u, q, o);
    }
    float mean = s*(1.f/256.f);
    float var  = q*(1.f/256.f) - mean*mean;
    float istd = rsqrtf(var + 1e-5f);
    int n = row & 511;
    float* hr = H + (size_t)row*256;
    const float* pr = pos + n*256;
    #pragma unroll
    for (int i = 0; i < 4; i++) {
        int p = i*32 + lane, c0 = 2*p;
        float y0 = (v[i].x-mean)*istd*g[c0]   + b[c0]   + pr[c0];
        float y1 = (v[i].y-mean)*istd*g[c0+1] + b[c0+1] + pr[c0+1];
        float2 o; o.x = y0; o.y = y1;
        *(float2*)&hr[c0] = o;
        split_pack(y0, y1, Hh[(size_t)row*128 + p], Hl[(size_t)row*128 + p]);
    }
}

// ---------------- BatchNorm finalize+apply fused ----------------
// 128 blocks x 256 threads; block covers 64 rows; thread (p,half) handles
// channel pair 2p,2p+1 for 32 rows. Finalize from BNP computed redundantly
// per block (BNP is L2-resident).
template<bool WF32>
__global__ __launch_bounds__(256) void bn_apply2_k(
    float* __restrict__ X, const float* __restrict__ part,
    const float* __restrict__ g, const float* __restrict__ b,
    uint32_t* __restrict__ Xh, uint32_t* __restrict__ Xl)
{
    int t = threadIdx.x;
    int p = t & 127;
    int half = t >> 7;
    int c0 = 2*p;
    float s0 = 0.f, s1 = 0.f, q0 = 0.f, q1 = 0.f;
    for (int i = 0; i < 64; i++) {
        float2 sv = *(const float2*)&part[i*256 + c0];
        float2 qv = *(const float2*)&part[16384 + i*256 + c0];
        s0 += sv.x; s1 += sv.y;
        q0 += qv.x; q1 += qv.y;
    }
    float m0 = s0*(1.f/8192.f), m1 = s1*(1.f/8192.f);
    float v0 = q0*(1.f/8192.f) - m0*m0;
    float v1 = q1*(1.f/8192.f) - m1*m1;
    float i0 = rsqrtf(v0 + 1e-5f), i1 = rsqrtf(v1 + 1e-5f);
    float sc0 = g[c0]*i0,   sh0 = b[c0]   - m0*sc0;
    float sc1 = g[c0+1]*i1, sh1 = b[c0+1] - m1*sc1;
    size_t r0 = (size_t)blockIdx.x*64 + half*32;
    for (int r = 0; r < 32; r++) {
        size_t row = r0 + r;
        float2 v = *(const float2*)&X[row*256 + c0];
        float y0 = v.x*sc0 + sh0;
        float y1 = v.y*sc1 + sh1;
        if (WF32) { float2 o; o.x = y0; o.y = y1; *(float2*)&X[row*256 + c0] = o; }
        split_pack(y0, y1, Xh[row*128 + p], Xl[row*128 + p]);
    }
}

// ---------------- block-sparse windowed attention (R11 exact) ----------------
__global__ __launch_bounds__(256) void attn_k(const float* __restrict__ QKV,
                                              uint32_t* __restrict__ AOh,
                                              uint32_t* __restrict__ AOl) {
    __shared__ float qs[32][33];
    __shared__ float kv[160][33];
    __shared__ float S[32][160];
    int bid = blockIdx.x;
    int qb = bid & 15, h = (bid >> 4) & 7, b = bid >> 7;
    int t = threadIdx.x;
    const float* base = QKV + (size_t)b*512*768;

    {
        int qr = t >> 3, e = (t & 7)*4;
        float4 v = *(const float4*)&base[(size_t)(qb*32 + qr)*768 + h*32 + e];
        qs[qr][e] = v.x; qs[qr][e+1] = v.y; qs[qr][e+2] = v.z; qs[qr][e+3] = v.w;
    }
    {
        int e = (t & 7)*4;
        for (int j = t >> 3; j < 160; j += 32) {
            int kb = qb + (j >> 5) - 2;
            float4 v = make_float4(0.f,0.f,0.f,0.f);
            if (kb >= 0 && kb < 16)
                v = *(const float4*)&base[(size_t)(kb*32 + (j & 31))*768 + 256 + h*32 + e];
            kv[j][e] = v.x; kv[j][e+1] = v.y; kv[j][e+2] = v.z; kv[j][e+3] = v.w;
        }
    }
    __syncthreads();

    const float scale = 0.17677669529663687f;
    {
        int qr = t >> 3;
        int j0 = (t & 7) * 20;
        float acc[20];
        #pragma unroll
        for (int jj = 0; jj < 20; jj++) acc[jj] = 0.f;
        #pragma unroll 4
        for (int k = 0; k < 32; k++) {
            float qv = qs[qr][k];
            #pragma unroll
            for (int jj = 0; jj < 20; jj++)
                acc[jj] += qv * kv[j0 + jj][k];
        }
        #pragma unroll
        for (int jj = 0; jj < 20; jj++) {
            int j = j0 + jj;
            int kb = qb + (j >> 5) - 2;
            S[qr][j] = (kb >= 0 && kb < 16) ? acc[jj]*scale : -1e9f;
        }
    }
    __syncthreads();

    {
        int warp = t >> 5, lane = t & 31;
        for (int qr = warp; qr < 32; qr += 8) {
            float vv[5]; float m = -1e30f;
            #pragma unroll
            for (int i = 0; i < 5; i++) { vv[i] = S[qr][lane + 32*i]; m = fmaxf(m, vv[i]); }
            #pragma unroll
            for (int o = 16; o; o >>= 1) m = fmaxf(m, __shfl_xor_sync(~0u, m, o));
            float s = 0.f;
            #pragma unroll
            for (int i = 0; i < 5; i++) { vv[i] = expf(vv[i] - m); s += vv[i]; }
            #pragma unroll
            for (int o = 16; o; o >>= 1) s += __shfl_xor_sync(~0u, s, o);
            float inv = 1.f/s;
            #pragma unroll
            for (int i = 0; i < 5; i++) S[qr][lane + 32*i] = vv[i]*inv;
        }
    }
    {
        int e = (t & 7)*4;
        for (int j = t >> 3; j < 160; j += 32) {
            int kb = qb + (j >> 5) - 2;
            float4 v = make_float4(0.f,0.f,0.f,0.f);
            if (kb >= 0 && kb < 16)
                v = *(const float4*)&base[(size_t)(kb*32 + (j & 31))*768 + 512 + h*32 + e];
            kv[j][e] = v.x; kv[j][e+1] = v.y; kv[j][e+2] = v.z; kv[j][e+3] = v.w;
        }
    }
    __syncthreads();

    #pragma unroll
    for (int ii = 0; ii < 2; ii++) {
        int idx = t + ii*256;
        int qr = idx >> 4, ep = idx & 15;
        int e0 = ep*2;
        float a0 = 0.f, a1 = 0.f;
        #pragma unroll 8
        for (int j = 0; j < 160; j++) {
            float p = S[qr][j];
            a0 += p*kv[j][e0];
            a1 += p*kv[j][e0+1];
        }
        size_t pi = (size_t)(b*512 + qb*32 + qr)*128 + h*16 + ep;
        split_pack(a0, a1, AOh[pi], AOl[pi]);
    }
}

// ---------------- fcl ----------------
__global__ __launch_bounds__(128) void fcl_part_k(
    const float* __restrict__ P, const float* __restrict__ W, float* __restrict__ out)
{
    __shared__ float As[16][128];
    int gch = blockIdx.x;
    int j = threadIdx.x;
    float acc[16];
    #pragma unroll
    for (int b = 0; b < 16; b++) acc[b] = 0.f;
    int k0 = gch*512;
    for (int s = 0; s < 4; s++) {
        int kb = k0 + s*128;
        __syncthreads();
        for (int idx = j; idx < 2048; idx += 128) {
            int b = idx >> 7, kk = idx & 127;
            As[b][kk] = P[(size_t)b*327680 + kb + kk];
        }
        __syncthreads();
        #pragma unroll 4
        for (int kk = 0; kk < 128; kk++) {
            float w = W[(size_t)(kb + kk)*128 + j];
            #pragma unroll
            for (int b = 0; b < 16; b++) acc[b] += As[b][kk]*w;
        }
    }
    #pragma unroll
    for (int b = 0; b < 16; b++) out[(size_t)gch*2048 + b*128 + j] = acc[b];
}

__global__ void fcl_red_k(const float* __restrict__ part, const float* __restrict__ bias,
                          float* __restrict__ add) {
    int idx = blockIdx.x*256 + threadIdx.x;
    int j = idx & 127;
    float s = 0.f;
    for (int gc = 0; gc < 640; gc++) s += part[(size_t)gc*2048 + idx];
    add[idx] = s + bias[j];
}

// ---------------- addbn + heads ----------------
__global__ __launch_bounds__(256) void heads_k(
    const float* __restrict__ add, const float* __restrict__ abg, const float* __restrict__ abb,
    const float* __restrict__ cW1, const float* __restrict__ cb1,
    const float* __restrict__ cW2, const float* __restrict__ cb2,
    const float* __restrict__ bW1, const float* __restrict__ bb1,
    const float* __restrict__ bW2, const float* __restrict__ bb2,
    float* __restrict__ out)
{
    __shared__ float sA[16][128];
    __shared__ float sH[16][256];
    __shared__ float sL[16][45];
    int t = threadIdx.x;
    if (t < 128) {
        float s = 0.f, q = 0.f;
        for (int b = 0; b < 16; b++) { float v = add[b*128 + t]; s += v; q += v*v; }
        float mean = s*(1.f/16.f);
        float var  = q*(1.f/16.f) - mean*mean;
        float istd = rsqrtf(var + 1e-5f);
        float sc = abg[t]*istd, sh = abb[t] - mean*sc;
        for (int b = 0; b < 16; b++) sA[b][t] = add[b*128 + t]*sc + sh;
    }
    __syncthreads();
    for (int idx = t; idx < 4096; idx += 256) {
        int b = idx >> 8, u = idx & 255;
        float a = cb1[u];
        for (int c = 0; c < 128; c++) a += sA[b][c]*cW1[c*256 + u];
        sH[b][u] = fmaxf(a, 0.f);
    }
    __syncthreads();
    for (int idx = t; idx < 720; idx += 256) {
        int b = idx/45, o = idx - b*45;
        float a = cb2[o];
        for (int u = 0; u < 256; u++) a += sH[b][u]*cW2[u*45 + o];
        sL[b][o] = a;
    }
    __syncthreads();
    if (t < 16) {
        int b = t;
        float m = -1e30f;
        for (int o = 0; o < 45; o++) m = fmaxf(m, sL[b][o]);
        float s = 0.f; float e[45];
        for (int o = 0; o < 45; o++) { e[o] = expf(sL[b][o] - m); s += e[o]; }
        float inv = 1.f/s;
        for (int o = 0; o < 45; o++)
            out[b*81 + (o/5)*9 + (o%5)] = e[o]*inv;
    }
    __syncthreads();
    for (int idx = t; idx < 2048; idx += 256) {
        int b = idx >> 7, u = idx & 127;
        float a = bb1[u];
        for (int c = 0; c < 128; c++) a += sA[b][c]*bW1[c*128 + u];
        sH[b][u] = fmaxf(a, 0.f);
    }
    __syncthreads();
    for (int idx = t; idx < 576; idx += 256) {
        int b = idx/36, o = idx - b*36;
        float a = bb2[o];
        for (int u = 0; u < 128; u++) a += sH[b][u]*bW2[u*36 + o];
        out[b*81 + (o/4)*9 + 5 + (o%4)] = a;
    }
}

// ---------------- host ----------------
extern "C" void kernel_launch(void* const* d_in, const int* in_sizes, int n_in,
                              void* d_out, int out_size) {
    const float* x       = (const float*)d_in[0];
    const float* patch_W = (const float*)d_in[1];
    const float* patch_b = (const float*)d_in[2];
    const float* ln_g    = (const float*)d_in[3];
    const float* ln_b    = (const float*)d_in[4];
    const float* ff_W1   = (const float*)d_in[5];
    const float* ff_b1   = (const float*)d_in[6];
    const float* ff_W2   = (const float*)d_in[7];
    const float* ff_b2   = (const float*)d_in[8];
    const float* Wqkv    = (const float*)d_in[9];
    const float* bqkv    = (const float*)d_in[10];
    const float* Wo      = (const float*)d_in[11];
    const float* bo      = (const float*)d_in[12];
    const float* bn1_g   = (const float*)d_in[13];
    const float* bn1_b   = (const float*)d_in[14];
    const float* bn2_g   = (const float*)d_in[15];
    const float* bn2_b   = (const float*)d_in[16];
    const float* pyr_W   = (const float*)d_in[17];
    const float* pyr_b   = (const float*)d_in[18];
    const float* fcl_W   = (const float*)d_in[19];
    const float* fcl_b   = (const float*)d_in[20];
    const float* addbn_g = (const float*)d_in[21];
    const float* addbn_b = (const float*)d_in[22];
    const float* cls_W1  = (const float*)d_in[23];
    const float* cls_b1  = (const float*)d_in[24];
    const float* cls_W2  = (const float*)d_in[25];
    const float* cls_b2  = (const float*)d_in[26];
    const float* box_W1  = (const float*)d_in[27];
    const float* box_b1  = (const float*)d_in[28];
    const float* box_W2  = (const float*)d_in[29];
    const float* box_b2  = (const float*)d_in[30];

    static float *X=nullptr,*T,*H,*QKV,*POS,*BNP,*PF,*FP,*ADD;
    static uint32_t *Xh,*Xl,*Hh,*Hl,*Th,*Tl,*Gh,*Gl,*Fh,*Fl,*AOh,*AOl;
    static uint32_t *Wph,*Wpl,*W1h,*W1l,*W2h,*W2l,*Wqh,*Wql,*Woh,*Wol,*Pyh,*Pyl;
    if (!X) {
        cudaGetSymbolAddress((void**)&X,  g_X);
        cudaGetSymbolAddress((void**)&T,  g_T);
        cudaGetSymbolAddress((void**)&H,  g_H);
        cudaGetSymbolAddress((void**)&QKV,g_QKV);
        cudaGetSymbolAddress((void**)&POS,g_POS);
        cudaGetSymbolAddress((void**)&BNP,g_BNP);
        cudaGetSymbolAddress((void**)&PF, g_PF);
        cudaGetSymbolAddress((void**)&FP, g_FP);
        cudaGetSymbolAddress((void**)&ADD,g_ADD);
        cudaGetSymbolAddress((void**)&Xh, g_Xh);  cudaGetSymbolAddress((void**)&Xl, g_Xl);
        cudaGetSymbolAddress((void**)&Hh, g_Hh);  cudaGetSymbolAddress((void**)&Hl, g_Hl);
        cudaGetSymbolAddress((void**)&Th, g_Th);  cudaGetSymbolAddress((void**)&Tl, g_Tl);
        cudaGetSymbolAddress((void**)&Gh, g_Gh);  cudaGetSymbolAddress((void**)&Gl, g_Gl);
        cudaGetSymbolAddress((void**)&Fh, g_Fh);  cudaGetSymbolAddress((void**)&Fl, g_Fl);
        cudaGetSymbolAddress((void**)&AOh,g_AOh); cudaGetSymbolAddress((void**)&AOl,g_AOl);
        cudaGetSymbolAddress((void**)&Wph,g_Wph); cudaGetSymbolAddress((void**)&Wpl,g_Wpl);
        cudaGetSymbolAddress((void**)&W1h,g_W1h); cudaGetSymbolAddress((void**)&W1l,g_W1l);
        cudaGetSymbolAddress((void**)&W2h,g_W2h); cudaGetSymbolAddress((void**)&W2l,g_W2l);
        cudaGetSymbolAddress((void**)&Wqh,g_Wqh); cudaGetSymbolAddress((void**)&Wql,g_Wql);
        cudaGetSymbolAddress((void**)&Woh,g_Woh); cudaGetSymbolAddress((void**)&Wol,g_Wol);
        cudaGetSymbolAddress((void**)&Pyh,g_Pyh); cudaGetSymbolAddress((void**)&Pyl,g_Pyl);
        cudaFuncSetAttribute(gemm_bf<E_NONE>, cudaFuncAttributeMaxDynamicSharedMemorySize, GSM_BYTES);
        cudaFuncSetAttribute(gemm_bf<E_GELU>, cudaFuncAttributeMaxDynamicSharedMemorySize, GSM_BYTES);
        cudaFuncSetAttribute(gemm_bf<E_ADD>,  cudaFuncAttributeMaxDynamicSharedMemorySize, GSM_BYTES);
        cudaFuncSetAttribute(gemm_bf<E_PYR>,  cudaFuncAttributeMaxDynamicSharedMemorySize, GSM_BYTES);
        cudaFuncSetAttribute(gemm_bf<E_CVT>,  cudaFuncAttributeMaxDynamicSharedMemorySize, GSM_BYTES);
    }

    pos_k<<<512,256>>>(POS);
    wcvt_all<<<1984,256>>>(patch_W, ff_W1, ff_W2, Wqkv, Wo, pyr_W,
                           Wph, Wpl, W1h, W1l, W2h, W2l,
                           Wqh, Wql, Woh, Wol, Pyh, Pyl);
    xcvt_k<<<4096,256>>>(x, Xh, Xl);

    for (int it = 0; it < 5; it++) {
        gemm_bf<E_NONE><<<dim3(2,64),256,GSM_BYTES>>>(Xh, Xl, Wph, Wpl, patch_b, nullptr, T, nullptr, nullptr, nullptr, MTOK, 256, 256, 0);
        ln_pos_k<<<1024,256>>>(T, ln_g, ln_b, POS, H, Hh, Hl);
        gemm_bf<E_GELU><<<dim3(8,64),256,GSM_BYTES>>>(Hh, Hl, W1h, W1l, ff_b1, nullptr, nullptr, Gh, Gl, nullptr, MTOK, 1024, 256, 0);
        gemm_bf<E_CVT><<<dim3(2,64),256,GSM_BYTES>>>(Gh, Gl, W2h, W2l, ff_b2, nullptr, nullptr, Fh, Fl, nullptr, MTOK, 256, 1024, 0);
        gemm_bf<E_NONE><<<dim3(6,64),256,GSM_BYTES>>>(Fh, Fl, Wqh, Wql, bqkv, nullptr, QKV, nullptr, nullptr, nullptr, MTOK, 768, 256, 0);
        attn_k<<<2048,256>>>(QKV, AOh, AOl);
        gemm_bf<E_ADD><<<dim3(2,64),256,GSM_BYTES>>>(AOh, AOl, Woh, Wol, bo, H, T, nullptr, nullptr, BNP, MTOK, 256, 256, 0);
        bn_apply2_k<true><<<128,256>>>(T, BNP, bn1_g, bn1_b, Th, Tl);
        gemm_bf<E_GELU><<<dim3(8,64),256,GSM_BYTES>>>(Th, Tl, W1h, W1l, ff_b1, nullptr, nullptr, Gh, Gl, nullptr, MTOK, 1024, 256, 0);
        gemm_bf<E_ADD><<<dim3(2,64),256,GSM_BYTES>>>(Gh, Gl, W2h, W2l, ff_b2, T, X, nullptr, nullptr, BNP, MTOK, 256, 1024, 0);
        bn_apply2_k<false><<<128,256>>>(X, BNP, bn2_g, bn2_b, Xh, Xl);
        gemm_bf<E_PYR><<<dim3(1,64),256,GSM_BYTES>>>(Xh, Xl, Pyh + it*16384, Pyl + it*16384, pyr_b + it*128,
                                                     nullptr, PF, nullptr, nullptr, nullptr, MTOK, 128, 256, it*65536);
    }

    fcl_part_k<<<640,128>>>(PF, fcl_W, FP);
    fcl_red_k<<<8,256>>>(FP, fcl_b, ADD);
    heads_k<<<1,256>>>(ADD, addbn_g, addbn_b,
                       cls_W1, cls_b1, cls_W2, cls_b2,
                       box_W1, box_b1, box_W2, box_b2,
                       (float*)d_out);
}

// round 16
// speedup vs baseline: 1.0245x; 1.0245x over previous
#include <cuda_runtime.h>
#include <cuda_bf16.h>
#include <math.h>
#include <stdint.h>

// ---------------- sizes ----------------
#define MTOK 8192
#define DMODEL 256
#define HID 1024

// ---------------- fp32 scratch ----------------
__device__ float g_X[MTOK*DMODEL];
__device__ float g_T[MTOK*DMODEL];
__device__ float g_H[MTOK*DMODEL];
__device__ float g_QKV[MTOK*3*DMODEL];
__device__ float g_POS[512*DMODEL];
__device__ float g_BNP[2*64*DMODEL];    // 64 M-band partials x 256 cols
__device__ float g_BNS[2*DMODEL];
__device__ float g_PF[16*327680];
__device__ float g_FP[640*16*128];
__device__ float g_ADD[16*128];

// ---------------- bf16 hi/lo packed-pair scratch ([m][k/2] uint32) --------
__device__ uint32_t g_Xh[MTOK*128], g_Xl[MTOK*128];
__device__ uint32_t g_Hh[MTOK*128], g_Hl[MTOK*128];
__device__ uint32_t g_Th[MTOK*128], g_Tl[MTOK*128];
__device__ uint32_t g_Gh[MTOK*512], g_Gl[MTOK*512];
__device__ uint32_t g_Fh[MTOK*128], g_Fl[MTOK*128];
__device__ uint32_t g_AOh[MTOK*128], g_AOl[MTOK*128];
__device__ uint32_t g_Wph[256*128],  g_Wpl[256*128];
__device__ uint32_t g_W1h[1024*128], g_W1l[1024*128];
__device__ uint32_t g_W2h[256*512],  g_W2l[256*512];
__device__ uint32_t g_Wqh[768*128],  g_Wql[768*128];
__device__ uint32_t g_Woh[256*128],  g_Wol[256*128];
__device__ uint32_t g_Pyh[5*128*128], g_Pyl[5*128*128];

// ---------------- helpers ----------------
__device__ __forceinline__ float gelu_tanh(float x) {
    float x3 = x*x*x;
    return 0.5f*x*(1.f + tanhf(0.7978845608028654f*(x + 0.044715f*x3)));
}

__device__ __forceinline__ void split_pack(float v0, float v1, uint32_t& ph, uint32_t& pl) {
    __nv_bfloat16 h0 = __float2bfloat16(v0), h1 = __float2bfloat16(v1);
    float r0 = v0 - __bfloat162float(h0), r1 = v1 - __bfloat162float(h1);
    __nv_bfloat16 l0 = __float2bfloat16(r0), l1 = __float2bfloat16(r1);
    ph = ((uint32_t)__bfloat16_as_ushort(h1) << 16) | (uint32_t)__bfloat16_as_ushort(h0);
    pl = ((uint32_t)__bfloat16_as_ushort(l1) << 16) | (uint32_t)__bfloat16_as_ushort(l0);
}

__device__ __forceinline__ void mma_bf16(float c[4],
    uint32_t a0, uint32_t a1, uint32_t a2, uint32_t a3, uint32_t b0, uint32_t b1)
{
    asm volatile(
        "mma.sync.aligned.m16n8k16.row.col.f32.bf16.bf16.f32 "
        "{%0,%1,%2,%3}, {%4,%5,%6,%7}, {%8,%9}, {%0,%1,%2,%3};\n"
        : "+f"(c[0]), "+f"(c[1]), "+f"(c[2]), "+f"(c[3])
        : "r"(a0), "r"(a1), "r"(a2), "r"(a3), "r"(b0), "r"(b1));
}

__device__ __forceinline__ uint32_t smem_u32(const void* p) {
    uint32_t a;
    asm("{ .reg .u64 t; cvta.to.shared.u64 t, %1; cvt.u32.u64 %0, t; }" : "=r"(a) : "l"(p));
    return a;
}

__device__ __forceinline__ void cp16(uint32_t dst, const void* src) {
    asm volatile("cp.async.cg.shared.global [%0], [%1], 16;" :: "r"(dst), "l"(src));
}

__device__ __forceinline__ void ldsm_x4(uint32_t r[4], uint32_t addr) {
    asm volatile("ldmatrix.sync.aligned.m8n8.x4.shared.b16 {%0,%1,%2,%3}, [%4];"
        : "=r"(r[0]), "=r"(r[1]), "=r"(r[2]), "=r"(r[3]) : "r"(addr));
}

// ---------------- one-shot weight conversion ----------------
__global__ void wcvt_all(
    const float* __restrict__ pW, const float* __restrict__ w1, const float* __restrict__ w2,
    const float* __restrict__ wq, const float* __restrict__ wo, const float* __restrict__ py,
    uint32_t* __restrict__ Wph, uint32_t* __restrict__ Wpl,
    uint32_t* __restrict__ W1h, uint32_t* __restrict__ W1l,
    uint32_t* __restrict__ W2h, uint32_t* __restrict__ W2l,
    uint32_t* __restrict__ Wqh, uint32_t* __restrict__ Wql,
    uint32_t* __restrict__ Woh, uint32_t* __restrict__ Wol,
    uint32_t* __restrict__ Pyh, uint32_t* __restrict__ Pyl)
{
    int idx = blockIdx.x*256 + threadIdx.x;
    const float* src; uint32_t *dh, *dl; int KP, N, li;
    if (idx < 32768)       { src = pW; dh = Wph; dl = Wpl; KP = 128; N = 256; li = idx; }
    else if (idx < 163840) { src = w1; dh = W1h; dl = W1l; KP = 128; N = 1024; li = idx - 32768; }
    else if (idx < 294912) { src = w2; dh = W2h; dl = W2l; KP = 512; N = 256; li = idx - 163840; }
    else if (idx < 393216) { src = wq; dh = Wqh; dl = Wql; KP = 128; N = 768; li = idx - 294912; }
    else if (idx < 425984) { src = wo; dh = Woh; dl = Wol; KP = 128; N = 256; li = idx - 393216; }
    else if (idx < 507904) {
        int r = idx - 425984;
        int l = r >> 14, rem = r & 16383;
        src = py + (size_t)l*32768; dh = Pyh + l*16384; dl = Pyl + l*16384;
        KP = 128; N = 128; li = rem;
    } else return;
    int n = li / KP, kp = li - n*KP;
    float v0 = src[(size_t)(2*kp)*N + n];
    float v1 = src[(size_t)(2*kp+1)*N + n];
    split_pack(v0, v1, dh[li], dl[li]);
}

__global__ void xcvt_k(const float* __restrict__ X, uint32_t* __restrict__ Xh,
                       uint32_t* __restrict__ Xl) {
    int idx = blockIdx.x*256 + threadIdx.x;
    float2 v = *(const float2*)&X[(size_t)idx*2];
    split_pack(v.x, v.y, Xh[idx], Xl[idx]);
}

// ---------------- positional table ----------------
__global__ void pos_k(float* __restrict__ pos) {
    int idx = blockIdx.x*256 + threadIdx.x;
    if (idx >= 512*256) return;
    int n = idx >> 8, d = idx & 255;
    double ang = (double)n / pow(10000.0, (double)(2*(d>>1)) / 256.0);
    pos[idx] = (float)((d & 1) ? cos(ang) : sin(ang));
}

// ---------------- bf16x3 tensor-core GEMM (R6 known-good) ----------------
// block 128x128, k-tile 32 (16 pairs), 8 warps (4M x 2N), warp tile 32x64
#define E_NONE 0
#define E_GELU 1
#define E_ADD  2
#define E_PYR  3
#define E_CVT  4

#define GST_W   10240
#define GARR_B  (2560*4)
#define GSM_BYTES (2*GST_W*4)

template<int EPI>
__global__ __launch_bounds__(256, 2) void gemm_bf(
    const uint32_t* __restrict__ Ahg, const uint32_t* __restrict__ Alg,
    const uint32_t* __restrict__ Bhg, const uint32_t* __restrict__ Blg,
    const float* __restrict__ bias, const float* __restrict__ R,
    float* __restrict__ C, uint32_t* __restrict__ Ch, uint32_t* __restrict__ Cl,
    float* __restrict__ BNPp, int M, int Nc, int K, int pyr_base)
{
    extern __shared__ uint32_t smem[];
    uint32_t sbase = smem_u32(smem);

    int t = threadIdx.x;
    int lane = t & 31, warp = t >> 5;
    int g = lane >> 2, tid4 = lane & 3;
    int warpM = (warp & 3) * 32;
    int warpN = (warp >> 2) * 64;
    int bm = blockIdx.y * 128, bn = blockIdx.x * 128;
    int KP = K >> 1;

    int rowA = (lane & 7) + ((lane >> 3) & 1) * 8;
    int kpA  = (lane >> 4) * 4;
    uint32_t aBase = sbase + (uint32_t)(((warpM + rowA)*20 + kpA) * 4);
    int rowB = (lane & 7) + (lane >> 4) * 8;
    int kpB  = ((lane >> 3) & 1) * 4;
    uint32_t bBase = sbase + 2u*GARR_B + (uint32_t)(((warpN + rowB)*20 + kpB) * 4);

    int c0r = t >> 2,        c0k = (t & 3) * 4;
    int c1r = (t + 256) >> 2, c1k = ((t + 256) & 3) * 4;

    float acc[2][8][4];
    #pragma unroll
    for (int i = 0; i < 2; i++)
        #pragma unroll
        for (int j = 0; j < 8; j++)
            #pragma unroll
            for (int r = 0; r < 4; r++) acc[i][j][r] = 0.f;

    int ntile = K >> 5;

    {
        uint32_t d0 = sbase + (uint32_t)((c0r*20 + c0k)*4);
        uint32_t d1 = sbase + (uint32_t)((c1r*20 + c1k)*4);
        cp16(d0,            Ahg + (size_t)(bm + c0r)*KP + c0k);
        cp16(d1,            Ahg + (size_t)(bm + c1r)*KP + c1k);
        cp16(d0 + GARR_B,   Alg + (size_t)(bm + c0r)*KP + c0k);
        cp16(d1 + GARR_B,   Alg + (size_t)(bm + c1r)*KP + c1k);
        cp16(d0 + 2*GARR_B, Bhg + (size_t)(bn + c0r)*KP + c0k);
        cp16(d1 + 2*GARR_B, Bhg + (size_t)(bn + c1r)*KP + c1k);
        cp16(d0 + 3*GARR_B, Blg + (size_t)(bn + c0r)*KP + c0k);
        cp16(d1 + 3*GARR_B, Blg + (size_t)(bn + c1r)*KP + c1k);
        asm volatile("cp.async.commit_group;");
    }

    for (int kt = 0; kt < ntile; kt++) {
        if (kt + 1 < ntile) {
            int kp0 = (kt + 1) * 16;
            uint32_t sb = sbase + (uint32_t)(((kt + 1) & 1) * GST_W * 4);
            uint32_t d0 = sb + (uint32_t)((c0r*20 + c0k)*4);
            uint32_t d1 = sb + (uint32_t)((c1r*20 + c1k)*4);
            cp16(d0,            Ahg + (size_t)(bm + c0r)*KP + kp0 + c0k);
            cp16(d1,            Ahg + (size_t)(bm + c1r)*KP + kp0 + c1k);
            cp16(d0 + GARR_B,   Alg + (size_t)(bm + c0r)*KP + kp0 + c0k);
            cp16(d1 + GARR_B,   Alg + (size_t)(bm + c1r)*KP + kp0 + c1k);
            cp16(d0 + 2*GARR_B, Bhg + (size_t)(bn + c0r)*KP + kp0 + c0k);
            cp16(d1 + 2*GARR_B, Bhg + (size_t)(bn + c1r)*KP + kp0 + c1k);
            cp16(d0 + 3*GARR_B, Blg + (size_t)(bn + c0r)*KP + kp0 + c0k);
            cp16(d1 + 3*GARR_B, Blg + (size_t)(bn + c1r)*KP + kp0 + c1k);
            asm volatile("cp.async.commit_group;");
            asm volatile("cp.async.wait_group 1;");
        } else {
            asm volatile("cp.async.wait_group 0;");
        }
        __syncthreads();

        uint32_t soff = (uint32_t)((kt & 1) * GST_W * 4);
        #pragma unroll
        for (int ko = 0; ko < 16; ko += 8) {
            uint32_t ah[2][4], al[2][4];
            #pragma unroll
            for (int mt = 0; mt < 2; mt++) {
                uint32_t aoff = soff + (uint32_t)((mt*16*20 + ko)*4);
                ldsm_x4(ah[mt], aBase + aoff);
                ldsm_x4(al[mt], aBase + aoff + GARR_B);
            }
            #pragma unroll
            for (int gb = 0; gb < 4; gb++) {
                uint32_t boff = soff + (uint32_t)((gb*16*20 + ko)*4);
                uint32_t bh[4], bl[4];
                ldsm_x4(bh, bBase + boff);
                ldsm_x4(bl, bBase + boff + GARR_B);
                #pragma unroll
                for (int half = 0; half < 2; half++) {
                    int nt = gb*2 + half;
                    uint32_t bh0 = bh[half*2], bh1 = bh[half*2+1];
                    uint32_t bl0 = bl[half*2], bl1 = bl[half*2+1];
                    #pragma unroll
                    for (int mt = 0; mt < 2; mt++) {
                        mma_bf16(acc[mt][nt], ah[mt][0], ah[mt][1], ah[mt][2], ah[mt][3], bh0, bh1);
                        mma_bf16(acc[mt][nt], ah[mt][0], ah[mt][1], ah[mt][2], ah[mt][3], bl0, bl1);
                        mma_bf16(acc[mt][nt], al[mt][0], al[mt][1], al[mt][2], al[mt][3], bh0, bh1);
                    }
                }
            }
        }
        __syncthreads();
    }

    float* sred = (float*)smem;
    int NP = Nc >> 1;
    #pragma unroll
    for (int nt = 0; nt < 8; nt++) {
        int col = bn + warpN + nt*8 + tid4*2;
        float bv0 = bias[col], bv1 = bias[col+1];
        float s0 = 0.f, q0 = 0.f, s1 = 0.f, q1 = 0.f;
        #pragma unroll
        for (int mt = 0; mt < 2; mt++) {
            #pragma unroll
            for (int h = 0; h < 2; h++) {
                int row = bm + warpM + mt*16 + g + h*8;
                float v0 = acc[mt][nt][h*2+0] + bv0;
                float v1 = acc[mt][nt][h*2+1] + bv1;
                if (EPI == E_GELU) { v0 = gelu_tanh(v0); v1 = gelu_tanh(v1); }
                if (EPI == E_ADD) {
                    float2 r = *(const float2*)&R[(size_t)row*Nc + col];
                    v0 += r.x; v1 += r.y;
                    s0 += v0; q0 += v0*v0; s1 += v1; q1 += v1*v1;
                }
                if (EPI == E_GELU || EPI == E_CVT) {
                    uint32_t ph, pl;
                    split_pack(v0, v1, ph, pl);
                    size_t pi = (size_t)row*NP + (col >> 1);
                    Ch[pi] = ph; Cl[pi] = pl;
                } else if (EPI == E_PYR) {
                    long b0 = (long)(row >> 9)*327680 + pyr_base + (row & 511);
                    C[b0 + (long)col*512]     = v0;
                    C[b0 + (long)(col+1)*512] = v1;
                } else {
                    float2 o; o.x = v0; o.y = v1;
                    *(float2*)&C[(size_t)row*Nc + col] = o;
                }
            }
        }
        if (EPI == E_ADD) {
            #pragma unroll
            for (int o = 4; o <= 16; o <<= 1) {
                s0 += __shfl_xor_sync(~0u, s0, o);
                q0 += __shfl_xor_sync(~0u, q0, o);
                s1 += __shfl_xor_sync(~0u, s1, o);
                q1 += __shfl_xor_sync(~0u, q1, o);
            }
            if (g == 0) {
                int cc = warpN + nt*8 + tid4*2;
                int strip = warp & 3;
                sred[strip*128 + cc]       = s0;
                sred[strip*128 + cc + 1]   = s1;
                sred[512 + strip*128 + cc]     = q0;
                sred[512 + strip*128 + cc + 1] = q1;
            }
        }
    }
    if (EPI == E_ADD) {
        __syncthreads();
        if (t < 128) {
            float s = sred[t] + sred[128 + t] + sred[256 + t] + sred[384 + t];
            BNPp[blockIdx.y*256 + blockIdx.x*128 + t] = s;
        } else if (t < 256) {
            int c = t - 128;
            float q = sred[512 + c] + sred[640 + c] + sred[768 + c] + sred[896 + c];
            BNPp[16384 + blockIdx.y*256 + blockIdx.x*128 + c] = q;
        }
    }
}

// ---------------- LayerNorm + pos ----------------
__global__ __launch_bounds__(256) void ln_pos_k(
    const float* __restrict__ T, const float* __restrict__ g,
    const float* __restrict__ b, const float* __restrict__ pos,
    float* __restrict__ H, uint32_t* __restrict__ Hh, uint32_t* __restrict__ Hl)
{
    int warp = threadIdx.x >> 5, lane = threadIdx.x & 31;
    int row = blockIdx.x*8 + warp;
    const float* tr = T + (size_t)row*256;
    float2 v[4]; float s = 0.f, q = 0.f;
    #pragma unroll
    for (int i = 0; i < 4; i++) {
        v[i] = *(const float2*)&tr[2*(i*32 + lane)];
        s += v[i].x + v[i].y; q += v[i].x*v[i].x + v[i].y*v[i].y;
    }
    #pragma unroll
    for (int o = 16; o; o >>= 1) {
        s += __shfl_xor_sync(~0u, s, o);
        q += __shfl_xor_sync(~0u, q, o);
    }
    float mean = s*(1.f/256.f);
    float var  = q*(1.f/256.f) - mean*mean;
    float istd = rsqrtf(var + 1e-5f);
    int n = row & 511;
    float* hr = H + (size_t)row*256;
    const float* pr = pos + n*256;
    #pragma unroll
    for (int i = 0; i < 4; i++) {
        int p = i*32 + lane, c0 = 2*p;
        float y0 = (v[i].x-mean)*istd*g[c0]   + b[c0]   + pr[c0];
        float y1 = (v[i].y-mean)*istd*g[c0+1] + b[c0+1] + pr[c0+1];
        float2 o; o.x = y0; o.y = y1;
        *(float2*)&hr[c0] = o;
        split_pack(y0, y1, Hh[(size_t)row*128 + p], Hl[(size_t)row*128 + p]);
    }
}

// ---------------- BatchNorm finalize/apply ----------------
__global__ void bn_fin_k(const float* __restrict__ part, const float* __restrict__ g,
                         const float* __restrict__ b, float* __restrict__ sc) {
    int c = threadIdx.x;
    float s = 0.f, q = 0.f;
    for (int i = 0; i < 64; i++) { s += part[i*256 + c]; q += part[16384 + i*256 + c]; }
    float mean = s*(1.f/8192.f);
    float var  = q*(1.f/8192.f) - mean*mean;
    float istd = rsqrtf(var + 1e-5f);
    float scale = g[c]*istd;
    sc[c] = scale;
    sc[256 + c] = b[c] - mean*scale;
}

template<bool WF32>
__global__ void bn_apply_k(float* __restrict__ X, const float* __restrict__ sc,
                           uint32_t* __restrict__ Xh, uint32_t* __restrict__ Xl) {
    int i = blockIdx.x*256 + threadIdx.x;
    float2 v = *(const float2*)&X[(size_t)i*2];
    int c = (i*2) & 255;
    float y0 = v.x*sc[c]   + sc[256+c];
    float y1 = v.y*sc[c+1] + sc[257+c];
    if (WF32) { float2 o; o.x = y0; o.y = y1; *(float2*)&X[(size_t)i*2] = o; }
    split_pack(y0, y1, Xh[i], Xl[i]);
}

// ---------------- block-sparse windowed attention ----------------
// scores phase register-blocked: thread owns (qr, 20 consecutive j)
__global__ __launch_bounds__(256) void attn_k(const float* __restrict__ QKV,
                                              uint32_t* __restrict__ AOh,
                                              uint32_t* __restrict__ AOl) {
    __shared__ float qs[32][33];
    __shared__ float kv[160][33];
    __shared__ float S[32][160];
    int bid = blockIdx.x;
    int qb = bid & 15, h = (bid >> 4) & 7, b = bid >> 7;
    int t = threadIdx.x;
    const float* base = QKV + (size_t)b*512*768;

    {
        int qr = t >> 3, e = (t & 7)*4;
        float4 v = *(const float4*)&base[(size_t)(qb*32 + qr)*768 + h*32 + e];
        qs[qr][e] = v.x; qs[qr][e+1] = v.y; qs[qr][e+2] = v.z; qs[qr][e+3] = v.w;
    }
    {
        int e = (t & 7)*4;
        for (int j = t >> 3; j < 160; j += 32) {
            int kb = qb + (j >> 5) - 2;
            float4 v = make_float4(0.f,0.f,0.f,0.f);
            if (kb >= 0 && kb < 16)
                v = *(const float4*)&base[(size_t)(kb*32 + (j & 31))*768 + 256 + h*32 + e];
            kv[j][e] = v.x; kv[j][e+1] = v.y; kv[j][e+2] = v.z; kv[j][e+3] = v.w;
        }
    }
    __syncthreads();

    const float scale = 0.17677669529663687f;
    {
        int qr = t >> 3;
        int j0 = (t & 7) * 20;
        float acc[20];
        #pragma unroll
        for (int jj = 0; jj < 20; jj++) acc[jj] = 0.f;
        #pragma unroll 4
        for (int k = 0; k < 32; k++) {
            float qv = qs[qr][k];
            #pragma unroll
            for (int jj = 0; jj < 20; jj++)
                acc[jj] += qv * kv[j0 + jj][k];
        }
        #pragma unroll
        for (int jj = 0; jj < 20; jj++) {
            int j = j0 + jj;
            int kb = qb + (j >> 5) - 2;
            S[qr][j] = (kb >= 0 && kb < 16) ? acc[jj]*scale : -1e9f;
        }
    }
    __syncthreads();

    {
        int warp = t >> 5, lane = t & 31;
        for (int qr = warp; qr < 32; qr += 8) {
            float vv[5]; float m = -1e30f;
            #pragma unroll
            for (int i = 0; i < 5; i++) { vv[i] = S[qr][lane + 32*i]; m = fmaxf(m, vv[i]); }
            #pragma unroll
            for (int o = 16; o; o >>= 1) m = fmaxf(m, __shfl_xor_sync(~0u, m, o));
            float s = 0.f;
            #pragma unroll
            for (int i = 0; i < 5; i++) { vv[i] = expf(vv[i] - m); s += vv[i]; }
            #pragma unroll
            for (int o = 16; o; o >>= 1) s += __shfl_xor_sync(~0u, s, o);
            float inv = 1.f/s;
            #pragma unroll
            for (int i = 0; i < 5; i++) S[qr][lane + 32*i] = vv[i]*inv;
        }
    }
    {
        int e = (t & 7)*4;
        for (int j = t >> 3; j < 160; j += 32) {
            int kb = qb + (j >> 5) - 2;
            float4 v = make_float4(0.f,0.f,0.f,0.f);
            if (kb >= 0 && kb < 16)
                v = *(const float4*)&base[(size_t)(kb*32 + (j & 31))*768 + 512 + h*32 + e];
            kv[j][e] = v.x; kv[j][e+1] = v.y; kv[j][e+2] = v.z; kv[j][e+3] = v.w;
        }
    }
    __syncthreads();

    #pragma unroll
    for (int ii = 0; ii < 2; ii++) {
        int idx = t + ii*256;
        int qr = idx >> 4, ep = idx & 15;
        int e0 = ep*2;
        float a0 = 0.f, a1 = 0.f;
        #pragma unroll 8
        for (int j = 0; j < 160; j++) {
            float p = S[qr][j];
            a0 += p*kv[j][e0];
            a1 += p*kv[j][e0+1];
        }
        size_t pi = (size_t)(b*512 + qb*32 + qr)*128 + h*16 + ep;
        split_pack(a0, a1, AOh[pi], AOl[pi]);
    }
}

// ---------------- fcl ----------------
__global__ __launch_bounds__(128) void fcl_part_k(
    const float* __restrict__ P, const float* __restrict__ W, float* __restrict__ out)
{
    __shared__ float As[16][128];
    int gch = blockIdx.x;
    int j = threadIdx.x;
    float acc[16];
    #pragma unroll
    for (int b = 0; b < 16; b++) acc[b] = 0.f;
    int k0 = gch*512;
    for (int s = 0; s < 4; s++) {
        int kb = k0 + s*128;
        __syncthreads();
        for (int idx = j; idx < 2048; idx += 128) {
            int b = idx >> 7, kk = idx & 127;
            As[b][kk] = P[(size_t)b*327680 + kb + kk];
        }
        __syncthreads();
        #pragma unroll 4
        for (int kk = 0; kk < 128; kk++) {
            float w = W[(size_t)(kb + kk)*128 + j];
            #pragma unroll
            for (int b = 0; b < 16; b++) acc[b] += As[b][kk]*w;
        }
    }
    #pragma unroll
    for (int b = 0; b < 16; b++) out[(size_t)gch*2048 + b*128 + j] = acc[b];
}

__global__ void fcl_red_k(const float* __restrict__ part, const float* __restrict__ bias,
                          float* __restrict__ add) {
    int idx = blockIdx.x*256 + threadIdx.x;
    int j = idx & 127;
    float s = 0.f;
    for (int gc = 0; gc < 640; gc++) s += part[(size_t)gc*2048 + idx];
    add[idx] = s + bias[j];
}

// ---------------- addbn + heads ----------------
__global__ __launch_bounds__(256) void heads_k(
    const float* __restrict__ add, const float* __restrict__ abg, const float* __restrict__ abb,
    const float* __restrict__ cW1, const float* __restrict__ cb1,
    const float* __restrict__ cW2, const float* __restrict__ cb2,
    const float* __restrict__ bW1, const float* __restrict__ bb1,
    const float* __restrict__ bW2, const float* __restrict__ bb2,
    float* __restrict__ out)
{
    __shared__ float sA[16][128];
    __shared__ float sH[16][256];
    __shared__ float sL[16][45];
    int t = threadIdx.x;
    if (t < 128) {
        float s = 0.f, q = 0.f;
        for (int b = 0; b < 16; b++) { float v = add[b*128 + t]; s += v; q += v*v; }
        float mean = s*(1.f/16.f);
        float var  = q*(1.f/16.f) - mean*mean;
        float istd = rsqrtf(var + 1e-5f);
        float sc = abg[t]*istd, sh = abb[t] - mean*sc;
        for (int b = 0; b < 16; b++) sA[b][t] = add[b*128 + t]*sc + sh;
    }
    __syncthreads();
    for (int idx = t; idx < 4096; idx += 256) {
        int b = idx >> 8, u = idx & 255;
        float a = cb1[u];
        for (int c = 0; c < 128; c++) a += sA[b][c]*cW1[c*256 + u];
        sH[b][u] = fmaxf(a, 0.f);
    }
    __syncthreads();
    for (int idx = t; idx < 720; idx += 256) {
        int b = idx/45, o = idx - b*45;
        float a = cb2[o];
        for (int u = 0; u < 256; u++) a += sH[b][u]*cW2[u*45 + o];
        sL[b][o] = a;
    }
    __syncthreads();
    if (t < 16) {
        int b = t;
        float m = -1e30f;
        for (int o = 0; o < 45; o++) m = fmaxf(m, sL[b][o]);
        float s = 0.f; float e[45];
        for (int o = 0; o < 45; o++) { e[o] = expf(sL[b][o] - m); s += e[o]; }
        float inv = 1.f/s;
        for (int o = 0; o < 45; o++)
            out[b*81 + (o/5)*9 + (o%5)] = e[o]*inv;
    }
    __syncthreads();
    for (int idx = t; idx < 2048; idx += 256) {
        int b = idx >> 7, u = idx & 127;
        float a = bb1[u];
        for (int c = 0; c < 128; c++) a += sA[b][c]*bW1[c*128 + u];
        sH[b][u] = fmaxf(a, 0.f);
    }
    __syncthreads();
    for (int idx = t; idx < 576; idx += 256) {
        int b = idx/36, o = idx - b*36;
        float a = bb2[o];
        for (int u = 0; u < 128; u++) a += sH[b][u]*bW2[u*36 + o];
        out[b*81 + (o/4)*9 + 5 + (o%4)] = a;
    }
}

// ---------------- host ----------------
extern "C" void kernel_launch(void* const* d_in, const int* in_sizes, int n_in,
                              void* d_out, int out_size) {
    const float* x       = (const float*)d_in[0];
    const float* patch_W = (const float*)d_in[1];
    const float* patch_b = (const float*)d_in[2];
    const float* ln_g    = (const float*)d_in[3];
    const float* ln_b    = (const float*)d_in[4];
    const float* ff_W1   = (const float*)d_in[5];
    const float* ff_b1   = (const float*)d_in[6];
    const float* ff_W2   = (const float*)d_in[7];
    const float* ff_b2   = (const float*)d_in[8];
    const float* Wqkv    = (const float*)d_in[9];
    const float* bqkv    = (const float*)d_in[10];
    const float* Wo      = (const float*)d_in[11];
    const float* bo      = (const float*)d_in[12];
    const float* bn1_g   = (const float*)d_in[13];
    const float* bn1_b   = (const float*)d_in[14];
    const float* bn2_g   = (const float*)d_in[15];
    const float* bn2_b   = (const float*)d_in[16];
    const float* pyr_W   = (const float*)d_in[17];
    const float* pyr_b   = (const float*)d_in[18];
    const float* fcl_W   = (const float*)d_in[19];
    const float* fcl_b   = (const float*)d_in[20];
    const float* addbn_g = (const float*)d_in[21];
    const float* addbn_b = (const float*)d_in[22];
    const float* cls_W1  = (const float*)d_in[23];
    const float* cls_b1  = (const float*)d_in[24];
    const float* cls_W2  = (const float*)d_in[25];
    const float* cls_b2  = (const float*)d_in[26];
    const float* box_W1  = (const float*)d_in[27];
    const float* box_b1  = (const float*)d_in[28];
    const float* box_W2  = (const float*)d_in[29];
    const float* box_b2  = (const float*)d_in[30];

    static float *X=nullptr,*T,*H,*QKV,*POS,*BNP,*BNS,*PF,*FP,*ADD;
    static uint32_t *Xh,*Xl,*Hh,*Hl,*Th,*Tl,*Gh,*Gl,*Fh,*Fl,*AOh,*AOl;
    static uint32_t *Wph,*Wpl,*W1h,*W1l,*W2h,*W2l,*Wqh,*Wql,*Woh,*Wol,*Pyh,*Pyl;
    if (!X) {
        cudaGetSymbolAddress((void**)&X,  g_X);
        cudaGetSymbolAddress((void**)&T,  g_T);
        cudaGetSymbolAddress((void**)&H,  g_H);
        cudaGetSymbolAddress((void**)&QKV,g_QKV);
        cudaGetSymbolAddress((void**)&POS,g_POS);
        cudaGetSymbolAddress((void**)&BNP,g_BNP);
        cudaGetSymbolAddress((void**)&BNS,g_BNS);
        cudaGetSymbolAddress((void**)&PF, g_PF);
        cudaGetSymbolAddress((void**)&FP, g_FP);
        cudaGetSymbolAddress((void**)&ADD,g_ADD);
        cudaGetSymbolAddress((void**)&Xh, g_Xh);  cudaGetSymbolAddress((void**)&Xl, g_Xl);
        cudaGetSymbolAddress((void**)&Hh, g_Hh);  cudaGetSymbolAddress((void**)&Hl, g_Hl);
        cudaGetSymbolAddress((void**)&Th, g_Th);  cudaGetSymbolAddress((void**)&Tl, g_Tl);
        cudaGetSymbolAddress((void**)&Gh, g_Gh);  cudaGetSymbolAddress((void**)&Gl, g_Gl);
        cudaGetSymbolAddress((void**)&Fh, g_Fh);  cudaGetSymbolAddress((void**)&Fl, g_Fl);
        cudaGetSymbolAddress((void**)&AOh,g_AOh); cudaGetSymbolAddress((void**)&AOl,g_AOl);
        cudaGetSymbolAddress((void**)&Wph,g_Wph); cudaGetSymbolAddress((void**)&Wpl,g_Wpl);
        cudaGetSymbolAddress((void**)&W1h,g_W1h); cudaGetSymbolAddress((void**)&W1l,g_W1l);
        cudaGetSymbolAddress((void**)&W2h,g_W2h); cudaGetSymbolAddress((void**)&W2l,g_W2l);
        cudaGetSymbolAddress((void**)&Wqh,g_Wqh); cudaGetSymbolAddress((void**)&Wql,g_Wql);
        cudaGetSymbolAddress((void**)&Woh,g_Woh); cudaGetSymbolAddress((void**)&Wol,g_Wol);
        cudaGetSymbolAddress((void**)&Pyh,g_Pyh); cudaGetSymbolAddress((void**)&Pyl,g_Pyl);
        cudaFuncSetAttribute(gemm_bf<E_NONE>, cudaFuncAttributeMaxDynamicSharedMemorySize, GSM_BYTES);
        cudaFuncSetAttribute(gemm_bf<E_GELU>, cudaFuncAttributeMaxDynamicSharedMemorySize, GSM_BYTES);
        cudaFuncSetAttribute(gemm_bf<E_ADD>,  cudaFuncAttributeMaxDynamicSharedMemorySize, GSM_BYTES);
        cudaFuncSetAttribute(gemm_bf<E_PYR>,  cudaFuncAttributeMaxDynamicSharedMemorySize, GSM_BYTES);
        cudaFuncSetAttribute(gemm_bf<E_CVT>,  cudaFuncAttributeMaxDynamicSharedMemorySize, GSM_BYTES);
    }

    pos_k<<<512,256>>>(POS);
    wcvt_all<<<1984,256>>>(patch_W, ff_W1, ff_W2, Wqkv, Wo, pyr_W,
                           Wph, Wpl, W1h, W1l, W2h, W2l,
                           Wqh, Wql, Woh, Wol, Pyh, Pyl);
    xcvt_k<<<4096,256>>>(x, Xh, Xl);

    for (int it = 0; it < 5; it++) {
        gemm_bf<E_NONE><<<dim3(2,64),256,GSM_BYTES>>>(Xh, Xl, Wph, Wpl, patch_b, nullptr, T, nullptr, nullptr, nullptr, MTOK, 256, 256, 0);
        ln_pos_k<<<1024,256>>>(T, ln_g, ln_b, POS, H, Hh, Hl);
        gemm_bf<E_GELU><<<dim3(8,64),256,GSM_BYTES>>>(Hh, Hl, W1h, W1l, ff_b1, nullptr, nullptr, Gh, Gl, nullptr, MTOK, 1024, 256, 0);
        gemm_bf<E_CVT><<<dim3(2,64),256,GSM_BYTES>>>(Gh, Gl, W2h, W2l, ff_b2, nullptr, nullptr, Fh, Fl, nullptr, MTOK, 256, 1024, 0);
        gemm_bf<E_NONE><<<dim3(6,64),256,GSM_BYTES>>>(Fh, Fl, Wqh, Wql, bqkv, nullptr, QKV, nullptr, nullptr, nullptr, MTOK, 768, 256, 0);
        attn_k<<<2048,256>>>(QKV, AOh, AOl);
        gemm_bf<E_ADD><<<dim3(2,64),256,GSM_BYTES>>>(AOh, AOl, Woh, Wol, bo, H, T, nullptr, nullptr, BNP, MTOK, 256, 256, 0);
        bn_fin_k<<<1,256>>>(BNP, bn1_g, bn1_b, BNS);
        bn_apply_k<true><<<4096,256>>>(T, BNS, Th, Tl);
        gemm_bf<E_GELU><<<dim3(8,64),256,GSM_BYTES>>>(Th, Tl, W1h, W1l, ff_b1, nullptr, nullptr, Gh, Gl, nullptr, MTOK, 1024, 256, 0);
        gemm_bf<E_ADD><<<dim3(2,64),256,GSM_BYTES>>>(Gh, Gl, W2h, W2l, ff_b2, T, X, nullptr, nullptr, BNP, MTOK, 256, 1024, 0);
        bn_fin_k<<<1,256>>>(BNP, bn2_g, bn2_b, BNS);
        bn_apply_k<false><<<4096,256>>>(X, BNS, Xh, Xl);
        gemm_bf<E_PYR><<<dim3(1,64),256,GSM_BYTES>>>(Xh, Xl, Pyh + it*16384, Pyl + it*16384, pyr_b + it*128,
                                                     nullptr, PF, nullptr, nullptr, nullptr, MTOK, 128, 256, it*65536);
    }

    fcl_part_k<<<640,128>>>(PF, fcl_W, FP);
    fcl_red_k<<<8,256>>>(FP, fcl_b, ADD);
    heads_k<<<1,256>>>(ADD, addbn_g, addbn_b,
                       cls_W1, cls_b1, cls_W2, cls_b2,
                       box_W1, box_b1, box_W2, box_b2,
                       (float*)d_out);
}

// round 17
// speedup vs baseline: 1.0267x; 1.0021x over previous
#include <cuda_runtime.h>
#include <cuda_bf16.h>
#include <math.h>
#include <stdint.h>

// ---------------- sizes ----------------
#define MTOK 8192
#define DMODEL 256
#define HID 1024

// ---------------- fp32 scratch ----------------
__device__ float g_X[MTOK*DMODEL];
__device__ float g_T[MTOK*DMODEL];
__device__ float g_H[MTOK*DMODEL];
__device__ float g_QKV[MTOK*3*DMODEL];
__device__ float g_POS[512*DMODEL];
__device__ float g_BNP[2*64*DMODEL];
__device__ float g_BNS[2*DMODEL];
__device__ float g_PF[16*327680];
__device__ float g_FP[640*16*128];
__device__ float g_ADD[16*128];

// ---------------- bf16 hi/lo packed-pair scratch ([m][k/2] uint32) --------
__device__ uint32_t g_Xh[MTOK*128], g_Xl[MTOK*128];
__device__ uint32_t g_Hh[MTOK*128], g_Hl[MTOK*128];
__device__ uint32_t g_Th[MTOK*128], g_Tl[MTOK*128];
__device__ uint32_t g_Gh[MTOK*512], g_Gl[MTOK*512];
__device__ uint32_t g_Fh[MTOK*128], g_Fl[MTOK*128];
__device__ uint32_t g_AOh[MTOK*128], g_AOl[MTOK*128];
__device__ uint32_t g_Wph[256*128],  g_Wpl[256*128];
__device__ uint32_t g_W1h[1024*128], g_W1l[1024*128];
__device__ uint32_t g_W2h[256*512],  g_W2l[256*512];
__device__ uint32_t g_Wqh[768*128],  g_Wql[768*128];
__device__ uint32_t g_Woh[256*128],  g_Wol[256*128];
__device__ uint32_t g_Pyh[5*128*128], g_Pyl[5*128*128];

// ---------------- helpers ----------------
__device__ __forceinline__ float gelu_tanh(float x) {
    float x3 = x*x*x;
    return 0.5f*x*(1.f + tanhf(0.7978845608028654f*(x + 0.044715f*x3)));
}

__device__ __forceinline__ void split_pack(float v0, float v1, uint32_t& ph, uint32_t& pl) {
    __nv_bfloat16 h0 = __float2bfloat16(v0), h1 = __float2bfloat16(v1);
    float r0 = v0 - __bfloat162float(h0), r1 = v1 - __bfloat162float(h1);
    __nv_bfloat16 l0 = __float2bfloat16(r0), l1 = __float2bfloat16(r1);
    ph = ((uint32_t)__bfloat16_as_ushort(h1) << 16) | (uint32_t)__bfloat16_as_ushort(h0);
    pl = ((uint32_t)__bfloat16_as_ushort(l1) << 16) | (uint32_t)__bfloat16_as_ushort(l0);
}

__device__ __forceinline__ void mma_bf16(float c[4],
    uint32_t a0, uint32_t a1, uint32_t a2, uint32_t a3, uint32_t b0, uint32_t b1)
{
    asm volatile(
        "mma.sync.aligned.m16n8k16.row.col.f32.bf16.bf16.f32 "
        "{%0,%1,%2,%3}, {%4,%5,%6,%7}, {%8,%9}, {%0,%1,%2,%3};\n"
        : "+f"(c[0]), "+f"(c[1]), "+f"(c[2]), "+f"(c[3])
        : "r"(a0), "r"(a1), "r"(a2), "r"(a3), "r"(b0), "r"(b1));
}

__device__ __forceinline__ uint32_t smem_u32(const void* p) {
    uint32_t a;
    asm("{ .reg .u64 t; cvta.to.shared.u64 t, %1; cvt.u32.u64 %0, t; }" : "=r"(a) : "l"(p));
    return a;
}

__device__ __forceinline__ void cp16(uint32_t dst, const void* src) {
    asm volatile("cp.async.cg.shared.global [%0], [%1], 16;" :: "r"(dst), "l"(src));
}

__device__ __forceinline__ void ldsm_x4(uint32_t r[4], uint32_t addr) {
    asm volatile("ldmatrix.sync.aligned.m8n8.x4.shared.b16 {%0,%1,%2,%3}, [%4];"
        : "=r"(r[0]), "=r"(r[1]), "=r"(r[2]), "=r"(r[3]) : "r"(addr));
}

// ---------------- one-shot weight conversion ----------------
__global__ void wcvt_all(
    const float* __restrict__ pW, const float* __restrict__ w1, const float* __restrict__ w2,
    const float* __restrict__ wq, const float* __restrict__ wo, const float* __restrict__ py,
    uint32_t* __restrict__ Wph, uint32_t* __restrict__ Wpl,
    uint32_t* __restrict__ W1h, uint32_t* __restrict__ W1l,
    uint32_t* __restrict__ W2h, uint32_t* __restrict__ W2l,
    uint32_t* __restrict__ Wqh, uint32_t* __restrict__ Wql,
    uint32_t* __restrict__ Woh, uint32_t* __restrict__ Wol,
    uint32_t* __restrict__ Pyh, uint32_t* __restrict__ Pyl)
{
    int idx = blockIdx.x*256 + threadIdx.x;
    const float* src; uint32_t *dh, *dl; int KP, N, li;
    if (idx < 32768)       { src = pW; dh = Wph; dl = Wpl; KP = 128; N = 256; li = idx; }
    else if (idx < 163840) { src = w1; dh = W1h; dl = W1l; KP = 128; N = 1024; li = idx - 32768; }
    else if (idx < 294912) { src = w2; dh = W2h; dl = W2l; KP = 512; N = 256; li = idx - 163840; }
    else if (idx < 393216) { src = wq; dh = Wqh; dl = Wql; KP = 128; N = 768; li = idx - 294912; }
    else if (idx < 425984) { src = wo; dh = Woh; dl = Wol; KP = 128; N = 256; li = idx - 393216; }
    else if (idx < 507904) {
        int r = idx - 425984;
        int l = r >> 14, rem = r & 16383;
        src = py + (size_t)l*32768; dh = Pyh + l*16384; dl = Pyl + l*16384;
        KP = 128; N = 128; li = rem;
    } else return;
    int n = li / KP, kp = li - n*KP;
    float v0 = src[(size_t)(2*kp)*N + n];
    float v1 = src[(size_t)(2*kp+1)*N + n];
    split_pack(v0, v1, dh[li], dl[li]);
}

__global__ void xcvt_k(const float* __restrict__ X, uint32_t* __restrict__ Xh,
                       uint32_t* __restrict__ Xl) {
    int idx = blockIdx.x*256 + threadIdx.x;
    float2 v = *(const float2*)&X[(size_t)idx*2];
    split_pack(v.x, v.y, Xh[idx], Xl[idx]);
}

// ---------------- positional table ----------------
__global__ void pos_k(float* __restrict__ pos) {
    int idx = blockIdx.x*256 + threadIdx.x;
    if (idx >= 512*256) return;
    int n = idx >> 8, d = idx & 255;
    double ang = (double)n / pow(10000.0, (double)(2*(d>>1)) / 256.0);
    pos[idx] = (float)((d & 1) ? cos(ang) : sin(ang));
}

// ---------------- bf16x3 tensor-core GEMM, NS-stage cp.async pipeline -----
#define E_NONE 0
#define E_GELU 1
#define E_ADD  2
#define E_PYR  3
#define E_CVT  4

#define GST_W   10240
#define GARR_B  (2560*4)
#define GSM2 (2*GST_W*4)
#define GSM3 (3*GST_W*4)

template<int EPI, int NS>
__global__ __launch_bounds__(256, 2) void gemm_bf(
    const uint32_t* __restrict__ Ahg, const uint32_t* __restrict__ Alg,
    const uint32_t* __restrict__ Bhg, const uint32_t* __restrict__ Blg,
    const float* __restrict__ bias, const float* __restrict__ R,
    float* __restrict__ C, uint32_t* __restrict__ Ch, uint32_t* __restrict__ Cl,
    float* __restrict__ BNPp, int M, int Nc, int K, int pyr_base)
{
    extern __shared__ uint32_t smem[];
    uint32_t sbase = smem_u32(smem);

    int t = threadIdx.x;
    int lane = t & 31, warp = t >> 5;
    int g = lane >> 2, tid4 = lane & 3;
    int warpM = (warp & 3) * 32;
    int warpN = (warp >> 2) * 64;
    int bm = blockIdx.y * 128, bn = blockIdx.x * 128;
    int KP = K >> 1;

    int rowA = (lane & 7) + ((lane >> 3) & 1) * 8;
    int kpA  = (lane >> 4) * 4;
    uint32_t aBase = sbase + (uint32_t)(((warpM + rowA)*20 + kpA) * 4);
    int rowB = (lane & 7) + (lane >> 4) * 8;
    int kpB  = ((lane >> 3) & 1) * 4;
    uint32_t bBase = sbase + 2u*GARR_B + (uint32_t)(((warpN + rowB)*20 + kpB) * 4);

    int c0r = t >> 2,        c0k = (t & 3) * 4;
    int c1r = (t + 256) >> 2, c1k = ((t + 256) & 3) * 4;

    float acc[2][8][4];
    #pragma unroll
    for (int i = 0; i < 2; i++)
        #pragma unroll
        for (int j = 0; j < 8; j++)
            #pragma unroll
            for (int r = 0; r < 4; r++) acc[i][j][r] = 0.f;

    int ntile = K >> 5;

    auto stage_load = [&](int stg, int kp0) {
        uint32_t sb = sbase + (uint32_t)(stg * GST_W * 4);
        uint32_t d0 = sb + (uint32_t)((c0r*20 + c0k)*4);
        uint32_t d1 = sb + (uint32_t)((c1r*20 + c1k)*4);
        cp16(d0,            Ahg + (size_t)(bm + c0r)*KP + kp0 + c0k);
        cp16(d1,            Ahg + (size_t)(bm + c1r)*KP + kp0 + c1k);
        cp16(d0 + GARR_B,   Alg + (size_t)(bm + c0r)*KP + kp0 + c0k);
        cp16(d1 + GARR_B,   Alg + (size_t)(bm + c1r)*KP + kp0 + c1k);
        cp16(d0 + 2*GARR_B, Bhg + (size_t)(bn + c0r)*KP + kp0 + c0k);
        cp16(d1 + 2*GARR_B, Bhg + (size_t)(bn + c1r)*KP + kp0 + c1k);
        cp16(d0 + 3*GARR_B, Blg + (size_t)(bn + c0r)*KP + kp0 + c0k);
        cp16(d1 + 3*GARR_B, Blg + (size_t)(bn + c1r)*KP + kp0 + c1k);
        asm volatile("cp.async.commit_group;");
    };

    stage_load(0, 0);
    if (NS == 3 && ntile > 1) stage_load(1, 16);

    for (int kt = 0; kt < ntile; kt++) {
        int nxt = kt + NS - 1;
        if (nxt < ntile) stage_load(nxt % NS, nxt * 16);
        if (NS == 2) {
            if (kt + 1 < ntile) { asm volatile("cp.async.wait_group 1;"); }
            else                { asm volatile("cp.async.wait_group 0;"); }
        } else {
            if (kt + 2 < ntile)      { asm volatile("cp.async.wait_group 2;"); }
            else if (kt + 1 < ntile) { asm volatile("cp.async.wait_group 1;"); }
            else                     { asm volatile("cp.async.wait_group 0;"); }
        }
        __syncthreads();

        uint32_t soff = (uint32_t)((kt % NS) * GST_W * 4);
        #pragma unroll
        for (int ko = 0; ko < 16; ko += 8) {
            uint32_t ah[2][4], al[2][4];
            #pragma unroll
            for (int mt = 0; mt < 2; mt++) {
                uint32_t aoff = soff + (uint32_t)((mt*16*20 + ko)*4);
                ldsm_x4(ah[mt], aBase + aoff);
                ldsm_x4(al[mt], aBase + aoff + GARR_B);
            }
            #pragma unroll
            for (int gb = 0; gb < 4; gb++) {
                uint32_t boff = soff + (uint32_t)((gb*16*20 + ko)*4);
                uint32_t bh[4], bl[4];
                ldsm_x4(bh, bBase + boff);
                ldsm_x4(bl, bBase + boff + GARR_B);
                #pragma unroll
                for (int half = 0; half < 2; half++) {
                    int nt = gb*2 + half;
                    uint32_t bh0 = bh[half*2], bh1 = bh[half*2+1];
                    uint32_t bl0 = bl[half*2], bl1 = bl[half*2+1];
                    #pragma unroll
                    for (int mt = 0; mt < 2; mt++) {
                        mma_bf16(acc[mt][nt], ah[mt][0], ah[mt][1], ah[mt][2], ah[mt][3], bh0, bh1);
                        mma_bf16(acc[mt][nt], ah[mt][0], ah[mt][1], ah[mt][2], ah[mt][3], bl0, bl1);
                        mma_bf16(acc[mt][nt], al[mt][0], al[mt][1], al[mt][2], al[mt][3], bh0, bh1);
                    }
                }
            }
        }
        __syncthreads();
    }

    float* sred = (float*)smem;
    int NP = Nc >> 1;
    #pragma unroll
    for (int nt = 0; nt < 8; nt++) {
        int col = bn + warpN + nt*8 + tid4*2;
        float bv0 = bias[col], bv1 = bias[col+1];
        float s0 = 0.f, q0 = 0.f, s1 = 0.f, q1 = 0.f;
        #pragma unroll
        for (int mt = 0; mt < 2; mt++) {
            #pragma unroll
            for (int h = 0; h < 2; h++) {
                int row = bm + warpM + mt*16 + g + h*8;
                float v0 = acc[mt][nt][h*2+0] + bv0;
                float v1 = acc[mt][nt][h*2+1] + bv1;
                if (EPI == E_GELU) { v0 = gelu_tanh(v0); v1 = gelu_tanh(v1); }
                if (EPI == E_ADD) {
                    float2 r = *(const float2*)&R[(size_t)row*Nc + col];
                    v0 += r.x; v1 += r.y;
                    s0 += v0; q0 += v0*v0; s1 += v1; q1 += v1*v1;
                }
                if (EPI == E_GELU || EPI == E_CVT) {
                    uint32_t ph, pl;
                    split_pack(v0, v1, ph, pl);
                    size_t pi = (size_t)row*NP + (col >> 1);
                    Ch[pi] = ph; Cl[pi] = pl;
                } else if (EPI == E_PYR) {
                    long b0 = (long)(row >> 9)*327680 + pyr_base + (row & 511);
                    C[b0 + (long)col*512]     = v0;
                    C[b0 + (long)(col+1)*512] = v1;
                } else {
                    float2 o; o.x = v0; o.y = v1;
                    *(float2*)&C[(size_t)row*Nc + col] = o;
                }
            }
        }
        if (EPI == E_ADD) {
            #pragma unroll
            for (int o = 4; o <= 16; o <<= 1) {
                s0 += __shfl_xor_sync(~0u, s0, o);
                q0 += __shfl_xor_sync(~0u, q0, o);
                s1 += __shfl_xor_sync(~0u, s1, o);
                q1 += __shfl_xor_sync(~0u, q1, o);
            }
            if (g == 0) {
                int cc = warpN + nt*8 + tid4*2;
                int strip = warp & 3;
                sred[strip*128 + cc]       = s0;
                sred[strip*128 + cc + 1]   = s1;
                sred[512 + strip*128 + cc]     = q0;
                sred[512 + strip*128 + cc + 1] = q1;
            }
        }
    }
    if (EPI == E_ADD) {
        __syncthreads();
        if (t < 128) {
            float s = sred[t] + sred[128 + t] + sred[256 + t] + sred[384 + t];
            BNPp[blockIdx.y*256 + blockIdx.x*128 + t] = s;
        } else if (t < 256) {
            int c = t - 128;
            float q = sred[512 + c] + sred[640 + c] + sred[768 + c] + sred[896 + c];
            BNPp[16384 + blockIdx.y*256 + blockIdx.x*128 + c] = q;
        }
    }
}

// ---------------- LayerNorm + pos ----------------
__global__ __launch_bounds__(256) void ln_pos_k(
    const float* __restrict__ T, const float* __restrict__ g,
    const float* __restrict__ b, const float* __restrict__ pos,
    float* __restrict__ H, uint32_t* __restrict__ Hh, uint32_t* __restrict__ Hl)
{
    int warp = threadIdx.x >> 5, lane = threadIdx.x & 31;
    int row = blockIdx.x*8 + warp;
    const float* tr = T + (size_t)row*256;
    float2 v[4]; float s = 0.f, q = 0.f;
    #pragma unroll
    for (int i = 0; i < 4; i++) {
        v[i] = *(const float2*)&tr[2*(i*32 + lane)];
        s += v[i].x + v[i].y; q += v[i].x*v[i].x + v[i].y*v[i].y;
    }
    #pragma unroll
    for (int o = 16; o; o >>= 1) {
        s += __shfl_xor_sync(~0u, s, o);
        q += __shfl_xor_sync(~0u, q, o);
    }
    float mean = s*(1.f/256.f);
    float var  = q*(1.f/256.f) - mean*mean;
    float istd = rsqrtf(var + 1e-5f);
    int n = row & 511;
    float* hr = H + (size_t)row*256;
    const float* pr = pos + n*256;
    #pragma unroll
    for (int i = 0; i < 4; i++) {
        int p = i*32 + lane, c0 = 2*p;
        float y0 = (v[i].x-mean)*istd*g[c0]   + b[c0]   + pr[c0];
        float y1 = (v[i].y-mean)*istd*g[c0+1] + b[c0+1] + pr[c0+1];
        float2 o; o.x = y0; o.y = y1;
        *(float2*)&hr[c0] = o;
        split_pack(y0, y1, Hh[(size_t)row*128 + p], Hl[(size_t)row*128 + p]);
    }
}

// ---------------- BatchNorm finalize/apply ----------------
__global__ void bn_fin_k(const float* __restrict__ part, const float* __restrict__ g,
                         const float* __restrict__ b, float* __restrict__ sc) {
    int c = threadIdx.x;
    float s = 0.f, q = 0.f;
    for (int i = 0; i < 64; i++) { s += part[i*256 + c]; q += part[16384 + i*256 + c]; }
    float mean = s*(1.f/8192.f);
    float var  = q*(1.f/8192.f) - mean*mean;
    float istd = rsqrtf(var + 1e-5f);
    float scale = g[c]*istd;
    sc[c] = scale;
    sc[256 + c] = b[c] - mean*scale;
}

template<bool WF32>
__global__ void bn_apply_k(float* __restrict__ X, const float* __restrict__ sc,
                           uint32_t* __restrict__ Xh, uint32_t* __restrict__ Xl) {
    int i = blockIdx.x*256 + threadIdx.x;
    float2 v = *(const float2*)&X[(size_t)i*2];
    int c = (i*2) & 255;
    float y0 = v.x*sc[c]   + sc[256+c];
    float y1 = v.y*sc[c+1] + sc[257+c];
    if (WF32) { float2 o; o.x = y0; o.y = y1; *(float2*)&X[(size_t)i*2] = o; }
    split_pack(y0, y1, Xh[i], Xl[i]);
}

// ---------------- block-sparse windowed attention (R11 exact) ----------------
__global__ __launch_bounds__(256) void attn_k(const float* __restrict__ QKV,
                                              uint32_t* __restrict__ AOh,
                                              uint32_t* __restrict__ AOl) {
    __shared__ float qs[32][33];
    __shared__ float kv[160][33];
    __shared__ float S[32][160];
    int bid = blockIdx.x;
    int qb = bid & 15, h = (bid >> 4) & 7, b = bid >> 7;
    int t = threadIdx.x;
    const float* base = QKV + (size_t)b*512*768;

    {
        int qr = t >> 3, e = (t & 7)*4;
        float4 v = *(const float4*)&base[(size_t)(qb*32 + qr)*768 + h*32 + e];
        qs[qr][e] = v.x; qs[qr][e+1] = v.y; qs[qr][e+2] = v.z; qs[qr][e+3] = v.w;
    }
    {
        int e = (t & 7)*4;
        for (int j = t >> 3; j < 160; j += 32) {
            int kb = qb + (j >> 5) - 2;
            float4 v = make_float4(0.f,0.f,0.f,0.f);
            if (kb >= 0 && kb < 16)
                v = *(const float4*)&base[(size_t)(kb*32 + (j & 31))*768 + 256 + h*32 + e];
            kv[j][e] = v.x; kv[j][e+1] = v.y; kv[j][e+2] = v.z; kv[j][e+3] = v.w;
        }
    }
    __syncthreads();

    const float scale = 0.17677669529663687f;
    {
        int qr = t >> 3;
        int j0 = (t & 7) * 20;
        float acc[20];
        #pragma unroll
        for (int jj = 0; jj < 20; jj++) acc[jj] = 0.f;
        #pragma unroll 4
        for (int k = 0; k < 32; k++) {
            float qv = qs[qr][k];
            #pragma unroll
            for (int jj = 0; jj < 20; jj++)
                acc[jj] += qv * kv[j0 + jj][k];
        }
        #pragma unroll
        for (int jj = 0; jj < 20; jj++) {
            int j = j0 + jj;
            int kb = qb + (j >> 5) - 2;
            S[qr][j] = (kb >= 0 && kb < 16) ? acc[jj]*scale : -1e9f;
        }
    }
    __syncthreads();

    {
        int warp = t >> 5, lane = t & 31;
        for (int qr = warp; qr < 32; qr += 8) {
            float vv[5]; float m = -1e30f;
            #pragma unroll
            for (int i = 0; i < 5; i++) { vv[i] = S[qr][lane + 32*i]; m = fmaxf(m, vv[i]); }
            #pragma unroll
            for (int o = 16; o; o >>= 1) m = fmaxf(m, __shfl_xor_sync(~0u, m, o));
            float s = 0.f;
            #pragma unroll
            for (int i = 0; i < 5; i++) { vv[i] = expf(vv[i] - m); s += vv[i]; }
            #pragma unroll
            for (int o = 16; o; o >>= 1) s += __shfl_xor_sync(~0u, s, o);
            float inv = 1.f/s;
            #pragma unroll
            for (int i = 0; i < 5; i++) S[qr][lane + 32*i] = vv[i]*inv;
        }
    }
    {
        int e = (t & 7)*4;
        for (int j = t >> 3; j < 160; j += 32) {
            int kb = qb + (j >> 5) - 2;
            float4 v = make_float4(0.f,0.f,0.f,0.f);
            if (kb >= 0 && kb < 16)
                v = *(const float4*)&base[(size_t)(kb*32 + (j & 31))*768 + 512 + h*32 + e];
            kv[j][e] = v.x; kv[j][e+1] = v.y; kv[j][e+2] = v.z; kv[j][e+3] = v.w;
        }
    }
    __syncthreads();

    #pragma unroll
    for (int ii = 0; ii < 2; ii++) {
        int idx = t + ii*256;
        int qr = idx >> 4, ep = idx & 15;
        int e0 = ep*2;
        float a0 = 0.f, a1 = 0.f;
        #pragma unroll 8
        for (int j = 0; j < 160; j++) {
            float p = S[qr][j];
            a0 += p*kv[j][e0];
            a1 += p*kv[j][e0+1];
        }
        size_t pi = (size_t)(b*512 + qb*32 + qr)*128 + h*16 + ep;
        split_pack(a0, a1, AOh[pi], AOl[pi]);
    }
}

// ---------------- fcl ----------------
__global__ __launch_bounds__(128) void fcl_part_k(
    const float* __restrict__ P, const float* __restrict__ W, float* __restrict__ out)
{
    __shared__ float As[16][128];
    int gch = blockIdx.x;
    int j = threadIdx.x;
    float acc[16];
    #pragma unroll
    for (int b = 0; b < 16; b++) acc[b] = 0.f;
    int k0 = gch*512;
    for (int s = 0; s < 4; s++) {
        int kb = k0 + s*128;
        __syncthreads();
        for (int idx = j; idx < 2048; idx += 128) {
            int b = idx >> 7, kk = idx & 127;
            As[b][kk] = P[(size_t)b*327680 + kb + kk];
        }
        __syncthreads();
        #pragma unroll 4
        for (int kk = 0; kk < 128; kk++) {
            float w = W[(size_t)(kb + kk)*128 + j];
            #pragma unroll
            for (int b = 0; b < 16; b++) acc[b] += As[b][kk]*w;
        }
    }
    #pragma unroll
    for (int b = 0; b < 16; b++) out[(size_t)gch*2048 + b*128 + j] = acc[b];
}

__global__ void fcl_red_k(const float* __restrict__ part, const float* __restrict__ bias,
                          float* __restrict__ add) {
    int idx = blockIdx.x*256 + threadIdx.x;
    int j = idx & 127;
    float s = 0.f;
    for (int gc = 0; gc < 640; gc++) s += part[(size_t)gc*2048 + idx];
    add[idx] = s + bias[j];
}

// ---------------- addbn + heads ----------------
__global__ __launch_bounds__(256) void heads_k(
    const float* __restrict__ add, const float* __restrict__ abg, const float* __restrict__ abb,
    const float* __restrict__ cW1, const float* __restrict__ cb1,
    const float* __restrict__ cW2, const float* __restrict__ cb2,
    const float* __restrict__ bW1, const float* __restrict__ bb1,
    const float* __restrict__ bW2, const float* __restrict__ bb2,
    float* __restrict__ out)
{
    __shared__ float sA[16][128];
    __shared__ float sH[16][256];
    __shared__ float sL[16][45];
    int t = threadIdx.x;
    if (t < 128) {
        float s = 0.f, q = 0.f;
        for (int b = 0; b < 16; b++) { float v = add[b*128 + t]; s += v; q += v*v; }
        float mean = s*(1.f/16.f);
        float var  = q*(1.f/16.f) - mean*mean;
        float istd = rsqrtf(var + 1e-5f);
        float sc = abg[t]*istd, sh = abb[t] - mean*sc;
        for (int b = 0; b < 16; b++) sA[b][t] = add[b*128 + t]*sc + sh;
    }
    __syncthreads();
    for (int idx = t; idx < 4096; idx += 256) {
        int b = idx >> 8, u = idx & 255;
        float a = cb1[u];
        for (int c = 0; c < 128; c++) a += sA[b][c]*cW1[c*256 + u];
        sH[b][u] = fmaxf(a, 0.f);
    }
    __syncthreads();
    for (int idx = t; idx < 720; idx += 256) {
        int b = idx/45, o = idx - b*45;
        float a = cb2[o];
        for (int u = 0; u < 256; u++) a += sH[b][u]*cW2[u*45 + o];
        sL[b][o] = a;
    }
    __syncthreads();
    if (t < 16) {
        int b = t;
        float m = -1e30f;
        for (int o = 0; o < 45; o++) m = fmaxf(m, sL[b][o]);
        float s = 0.f; float e[45];
        for (int o = 0; o < 45; o++) { e[o] = expf(sL[b][o] - m); s += e[o]; }
        float inv = 1.f/s;
        for (int o = 0; o < 45; o++)
            out[b*81 + (o/5)*9 + (o%5)] = e[o]*inv;
    }
    __syncthreads();
    for (int idx = t; idx < 2048; idx += 256) {
        int b = idx >> 7, u = idx & 127;
        float a = bb1[u];
        for (int c = 0; c < 128; c++) a += sA[b][c]*bW1[c*128 + u];
        sH[b][u] = fmaxf(a, 0.f);
    }
    __syncthreads();
    for (int idx = t; idx < 576; idx += 256) {
        int b = idx/36, o = idx - b*36;
        float a = bb2[o];
        for (int u = 0; u < 128; u++) a += sH[b][u]*bW2[u*36 + o];
        out[b*81 + (o/4)*9 + 5 + (o%4)] = a;
    }
}

// ---------------- host ----------------
extern "C" void kernel_launch(void* const* d_in, const int* in_sizes, int n_in,
                              void* d_out, int out_size) {
    const float* x       = (const float*)d_in[0];
    const float* patch_W = (const float*)d_in[1];
    const float* patch_b = (const float*)d_in[2];
    const float* ln_g    = (const float*)d_in[3];
    const float* ln_b    = (const float*)d_in[4];
    const float* ff_W1   = (const float*)d_in[5];
    const float* ff_b1   = (const float*)d_in[6];
    const float* ff_W2   = (const float*)d_in[7];
    const float* ff_b2   = (const float*)d_in[8];
    const float* Wqkv    = (const float*)d_in[9];
    const float* bqkv    = (const float*)d_in[10];
    const float* Wo      = (const float*)d_in[11];
    const float* bo      = (const float*)d_in[12];
    const float* bn1_g   = (const float*)d_in[13];
    const float* bn1_b   = (const float*)d_in[14];
    const float* bn2_g   = (const float*)d_in[15];
    const float* bn2_b   = (const float*)d_in[16];
    const float* pyr_W   = (const float*)d_in[17];
    const float* pyr_b   = (const float*)d_in[18];
    const float* fcl_W   = (const float*)d_in[19];
    const float* fcl_b   = (const float*)d_in[20];
    const float* addbn_g = (const float*)d_in[21];
    const float* addbn_b = (const float*)d_in[22];
    const float* cls_W1  = (const float*)d_in[23];
    const float* cls_b1  = (const float*)d_in[24];
    const float* cls_W2  = (const float*)d_in[25];
    const float* cls_b2  = (const float*)d_in[26];
    const float* box_W1  = (const float*)d_in[27];
    const float* box_b1  = (const float*)d_in[28];
    const float* box_W2  = (const float*)d_in[29];
    const float* box_b2  = (const float*)d_in[30];

    static float *X=nullptr,*T,*H,*QKV,*POS,*BNP,*BNS,*PF,*FP,*ADD;
    static uint32_t *Xh,*Xl,*Hh,*Hl,*Th,*Tl,*Gh,*Gl,*Fh,*Fl,*AOh,*AOl;
    static uint32_t *Wph,*Wpl,*W1h,*W1l,*W2h,*W2l,*Wqh,*Wql,*Woh,*Wol,*Pyh,*Pyl;
    if (!X) {
        cudaGetSymbolAddress((void**)&X,  g_X);
        cudaGetSymbolAddress((void**)&T,  g_T);
        cudaGetSymbolAddress((void**)&H,  g_H);
        cudaGetSymbolAddress((void**)&QKV,g_QKV);
        cudaGetSymbolAddress((void**)&POS,g_POS);
        cudaGetSymbolAddress((void**)&BNP,g_BNP);
        cudaGetSymbolAddress((void**)&BNS,g_BNS);
        cudaGetSymbolAddress((void**)&PF, g_PF);
        cudaGetSymbolAddress((void**)&FP, g_FP);
        cudaGetSymbolAddress((void**)&ADD,g_ADD);
        cudaGetSymbolAddress((void**)&Xh, g_Xh);  cudaGetSymbolAddress((void**)&Xl, g_Xl);
        cudaGetSymbolAddress((void**)&Hh, g_Hh);  cudaGetSymbolAddress((void**)&Hl, g_Hl);
        cudaGetSymbolAddress((void**)&Th, g_Th);  cudaGetSymbolAddress((void**)&Tl, g_Tl);
        cudaGetSymbolAddress((void**)&Gh, g_Gh);  cudaGetSymbolAddress((void**)&Gl, g_Gl);
        cudaGetSymbolAddress((void**)&Fh, g_Fh);  cudaGetSymbolAddress((void**)&Fl, g_Fl);
        cudaGetSymbolAddress((void**)&AOh,g_AOh); cudaGetSymbolAddress((void**)&AOl,g_AOl);
        cudaGetSymbolAddress((void**)&Wph,g_Wph); cudaGetSymbolAddress((void**)&Wpl,g_Wpl);
        cudaGetSymbolAddress((void**)&W1h,g_W1h); cudaGetSymbolAddress((void**)&W1l,g_W1l);
        cudaGetSymbolAddress((void**)&W2h,g_W2h); cudaGetSymbolAddress((void**)&W2l,g_W2l);
        cudaGetSymbolAddress((void**)&Wqh,g_Wqh); cudaGetSymbolAddress((void**)&Wql,g_Wql);
        cudaGetSymbolAddress((void**)&Woh,g_Woh); cudaGetSymbolAddress((void**)&Wol,g_Wol);
        cudaGetSymbolAddress((void**)&Pyh,g_Pyh); cudaGetSymbolAddress((void**)&Pyl,g_Pyl);
        cudaFuncSetAttribute(gemm_bf<E_NONE,3>, cudaFuncAttributeMaxDynamicSharedMemorySize, GSM3);
        cudaFuncSetAttribute(gemm_bf<E_CVT,3>,  cudaFuncAttributeMaxDynamicSharedMemorySize, GSM3);
        cudaFuncSetAttribute(gemm_bf<E_ADD,3>,  cudaFuncAttributeMaxDynamicSharedMemorySize, GSM3);
        cudaFuncSetAttribute(gemm_bf<E_PYR,3>,  cudaFuncAttributeMaxDynamicSharedMemorySize, GSM3);
        cudaFuncSetAttribute(gemm_bf<E_GELU,2>, cudaFuncAttributeMaxDynamicSharedMemorySize, GSM2);
        cudaFuncSetAttribute(gemm_bf<E_NONE,2>, cudaFuncAttributeMaxDynamicSharedMemorySize, GSM2);
    }

    pos_k<<<512,256>>>(POS);
    wcvt_all<<<1984,256>>>(patch_W, ff_W1, ff_W2, Wqkv, Wo, pyr_W,
                           Wph, Wpl, W1h, W1l, W2h, W2l,
                           Wqh, Wql, Woh, Wol, Pyh, Pyl);
    xcvt_k<<<4096,256>>>(x, Xh, Xl);

    for (int it = 0; it < 5; it++) {
        gemm_bf<E_NONE,3><<<dim3(2,64),256,GSM3>>>(Xh, Xl, Wph, Wpl, patch_b, nullptr, T, nullptr, nullptr, nullptr, MTOK, 256, 256, 0);
        ln_pos_k<<<1024,256>>>(T, ln_g, ln_b, POS, H, Hh, Hl);
        gemm_bf<E_GELU,2><<<dim3(8,64),256,GSM2>>>(Hh, Hl, W1h, W1l, ff_b1, nullptr, nullptr, Gh, Gl, nullptr, MTOK, 1024, 256, 0);
        gemm_bf<E_CVT,3><<<dim3(2,64),256,GSM3>>>(Gh, Gl, W2h, W2l, ff_b2, nullptr, nullptr, Fh, Fl, nullptr, MTOK, 256, 1024, 0);
        gemm_bf<E_NONE,2><<<dim3(6,64),256,GSM2>>>(Fh, Fl, Wqh, Wql, bqkv, nullptr, QKV, nullptr, nullptr, nullptr, MTOK, 768, 256, 0);
        attn_k<<<2048,256>>>(QKV, AOh, AOl);
        gemm_bf<E_ADD,3><<<dim3(2,64),256,GSM3>>>(AOh, AOl, Woh, Wol, bo, H, T, nullptr, nullptr, BNP, MTOK, 256, 256, 0);
        bn_fin_k<<<1,256>>>(BNP, bn1_g, bn1_b, BNS);
        bn_apply_k<true><<<4096,256>>>(T, BNS, Th, Tl);
        gemm_bf<E_GELU,2><<<dim3(8,64),256,GSM2>>>(Th, Tl, W1h, W1l, ff_b1, nullptr, nullptr, Gh, Gl, nullptr, MTOK, 1024, 256, 0);
        gemm_bf<E_ADD,3><<<dim3(2,64),256,GSM3>>>(Gh, Gl, W2h, W2l, ff_b2, T, X, nullptr, nullptr, BNP, MTOK, 256, 1024, 0);
        bn_fin_k<<<1,256>>>(BNP, bn2_g, bn2_b, BNS);
        bn_apply_k<false><<<4096,256>>>(X, BNS, Xh, Xl);
        gemm_bf<E_PYR,3><<<dim3(1,64),256,GSM3>>>(Xh, Xl, Pyh + it*16384, Pyl + it*16384, pyr_b + it*128,
                                                  nullptr, PF, nullptr, nullptr, nullptr, MTOK, 128, 256, it*65536);
    }

    fcl_part_k<<<640,128>>>(PF, fcl_W, FP);
    fcl_red_k<<<8,256>>>(FP, fcl_b, ADD);
    heads_k<<<1,256>>>(ADD, addbn_g, addbn_b,
                       cls_W1, cls_b1, cls_W2, cls_b2,
                       box_W1, box_b1, box_W2, box_b2,
                       (float*)d_out);
}